// round 1
// baseline (speedup 1.0000x reference)
#include <cuda_runtime.h>

#define Bc 2
#define Sc 2048
#define Dc 768
#define Hc 12
#define HDc 64
#define QSCALE 0.125f   // 64^-0.5

// Scratch (allocation-free): q/k/v in [B,H,S,HD], attention output in [B,S,H*HD]
__device__ float g_q[Bc * Hc * Sc * HDc];
__device__ float g_k[Bc * Hc * Sc * HDc];
__device__ float g_v[Bc * Hc * Sc * HDc];
__device__ float g_att[Bc * Sc * Dc];

// ---------------------------------------------------------------------------
// Tiled fp32 GEMM: C[M,N] = A[M,K] @ W[K,N] + bias[N]
// Block tile 64x64, BK=16, 256 threads, 4x4 micro-tile per thread.
// MODE 0: A = x, epilogue scatters into g_q (scaled) / g_k / g_v
// MODE 1: A = g_att, epilogue writes out[m*N+n]
// ---------------------------------------------------------------------------
template <int MODE>
__global__ __launch_bounds__(256)
void gemm64(const float* __restrict__ A, const float* __restrict__ W,
            const float* __restrict__ bias, float* __restrict__ out,
            int M, int N, int K)
{
    __shared__ float As[64][16];
    __shared__ float Bs[16][64];

    const int tid = threadIdx.x;
    const int tx = tid & 15;          // 0..15 (cols)
    const int ty = tid >> 4;          // 0..15 (rows)
    const int n0 = blockIdx.x * 64;
    const int row0 = blockIdx.y * 64;

    const float* Ap = (MODE == 0) ? A : (const float*)g_att;

    float acc[4][4];
#pragma unroll
    for (int i = 0; i < 4; i++)
#pragma unroll
        for (int j = 0; j < 4; j++) acc[i][j] = 0.f;

    for (int kk0 = 0; kk0 < K; kk0 += 16) {
#pragma unroll
        for (int i = 0; i < 4; i++) {
            int idx = tid + i * 256;            // 0..1023
            int r = idx >> 4, c = idx & 15;     // A tile 64x16
            As[r][c] = Ap[(size_t)(row0 + r) * K + kk0 + c];
        }
#pragma unroll
        for (int i = 0; i < 4; i++) {
            int idx = tid + i * 256;
            int r = idx >> 6, c = idx & 63;     // W tile 16x64
            Bs[r][c] = W[(size_t)(kk0 + r) * N + n0 + c];
        }
        __syncthreads();

#pragma unroll
        for (int kk = 0; kk < 16; kk++) {
            float a[4];
#pragma unroll
            for (int i = 0; i < 4; i++) a[i] = As[ty * 4 + i][kk];
            float4 bv = *(const float4*)&Bs[kk][tx * 4];
#pragma unroll
            for (int i = 0; i < 4; i++) {
                acc[i][0] += a[i] * bv.x;
                acc[i][1] += a[i] * bv.y;
                acc[i][2] += a[i] * bv.z;
                acc[i][3] += a[i] * bv.w;
            }
        }
        __syncthreads();
    }

#pragma unroll
    for (int i = 0; i < 4; i++) {
        int m = row0 + ty * 4 + i;
#pragma unroll
        for (int j = 0; j < 4; j++) {
            int n = n0 + tx * 4 + j;
            float v = acc[i][j] + bias[n];
            if (MODE == 0) {
                int which = n / Dc;            // 0=q 1=k 2=v
                int rr = n - which * Dc;
                int h = rr >> 6;
                int hd = rr & 63;
                int b = m >> 11;               // m / 2048
                int s = m & 2047;
                int idx = ((b * Hc + h) * Sc + s) * HDc + hd;
                if (which == 0)      g_q[idx] = v * QSCALE;
                else if (which == 1) g_k[idx] = v;
                else                 g_v[idx] = v;
            } else {
                out[(size_t)m * N + n] = v;
            }
        }
    }
}

// ---------------------------------------------------------------------------
// Flash-attention: one thread per query row (q, o register-resident, HD=64).
// K/V streamed through SMEM in 32-row tiles with online softmax.
// grid: (S/128, B*H), block: 128 threads.
// ---------------------------------------------------------------------------
__global__ __launch_bounds__(128)
void attn_kernel()
{
    __shared__ float Ks[32][64];
    __shared__ float Vs[32][64];

    const int bh = blockIdx.y;                      // 0..23
    const int srow = blockIdx.x * 128 + threadIdx.x; // 0..2047
    const int b = bh / Hc;
    const int h = bh - b * Hc;

    const float* qp = g_q + ((size_t)bh * Sc + srow) * HDc;
    const float* kbase = g_k + (size_t)bh * Sc * HDc;
    const float* vbase = g_v + (size_t)bh * Sc * HDc;

    float q[64];
#pragma unroll
    for (int d = 0; d < 64; d += 4) {
        float4 t = *(const float4*)(qp + d);
        q[d] = t.x; q[d + 1] = t.y; q[d + 2] = t.z; q[d + 3] = t.w;
    }

    float o[64];
#pragma unroll
    for (int d = 0; d < 64; d++) o[d] = 0.f;
    float mx = -1e30f;
    float l = 0.f;

    for (int kt = 0; kt < Sc; kt += 32) {
        __syncthreads();
        const float4* ksrc = (const float4*)(kbase + (size_t)kt * HDc);
        const float4* vsrc = (const float4*)(vbase + (size_t)kt * HDc);
#pragma unroll
        for (int i = 0; i < 4; i++) {
            int idx = threadIdx.x + i * 128;        // 0..511 float4s = 2048 floats
            ((float4*)Ks)[idx] = ksrc[idx];
            ((float4*)Vs)[idx] = vsrc[idx];
        }
        __syncthreads();

        for (int j = 0; j < 32; j++) {
            float s = 0.f;
#pragma unroll
            for (int d = 0; d < 64; d++) s += q[d] * Ks[j][d];

            if (s > mx) {
                float c = __expf(mx - s);
                l *= c;
#pragma unroll
                for (int d = 0; d < 64; d++) o[d] *= c;
                mx = s;
            }
            float p = __expf(s - mx);
            l += p;
#pragma unroll
            for (int d = 0; d < 64; d++) o[d] += p * Vs[j][d];
        }
    }

    float inv = 1.f / l;
    float* op = g_att + ((size_t)(b * Sc + srow)) * Dc + h * HDc;
#pragma unroll
    for (int d = 0; d < 64; d += 4) {
        float4 t;
        t.x = o[d] * inv; t.y = o[d + 1] * inv;
        t.z = o[d + 2] * inv; t.w = o[d + 3] * inv;
        *(float4*)(op + d) = t;
    }
}

// ---------------------------------------------------------------------------
extern "C" void kernel_launch(void* const* d_in, const int* in_sizes, int n_in,
                              void* d_out, int out_size)
{
    const float* x      = (const float*)d_in[0];   // [B,S,D]
    const float* w_qkv  = (const float*)d_in[1];   // [D,3D]
    const float* b_qkv  = (const float*)d_in[2];   // [3D]
    const float* w_proj = (const float*)d_in[3];   // [D,D]
    const float* b_proj = (const float*)d_in[4];   // [D]
    float* out = (float*)d_out;                    // [B,S,D]

    const int M = Bc * Sc;        // 4096

    // 1) QKV projection + scatter (q scaled)
    dim3 gq(3 * Dc / 64, M / 64); // (36, 64)
    gemm64<0><<<gq, 256>>>(x, w_qkv, b_qkv, nullptr, M, 3 * Dc, Dc);

    // 2) attention
    dim3 ga(Sc / 128, Bc * Hc);   // (16, 24)
    attn_kernel<<<ga, 128>>>();

    // 3) output projection
    dim3 gp(Dc / 64, M / 64);     // (12, 64)
    gemm64<1><<<gp, 256>>>(nullptr, w_proj, b_proj, out, M, Dc, Dc);
}

// round 3
// speedup vs baseline: 3.6671x; 3.6671x over previous
#include <cuda_runtime.h>

#define Bc 2
#define Sc 2048
#define Dc 768
#define Hc 12
#define HDc 64
#define QSCALE 0.125f   // 64^-0.5

// Scratch (allocation-free)
__device__ float g_q[Bc * Hc * Sc * HDc];
__device__ float g_k[Bc * Hc * Sc * HDc];
__device__ float g_v[Bc * Hc * Sc * HDc];
__device__ float g_att[Bc * Sc * Dc];

// ---------------------------------------------------------------------------
// tf32 helpers
// ---------------------------------------------------------------------------
__device__ __forceinline__ unsigned f2tf(float x) {
    unsigned u;
    asm("cvt.rna.tf32.f32 %0, %1;" : "=r"(u) : "f"(x));
    return u;
}

// D = A(16x8,row) @ B(8x8,col) + D   (tf32 in, f32 accum)
__device__ __forceinline__ void mma8(float c[4], const unsigned a[4],
                                     unsigned b0, unsigned b1) {
    asm volatile(
        "mma.sync.aligned.m16n8k8.row.col.f32.tf32.tf32.f32 "
        "{%0,%1,%2,%3},{%4,%5,%6,%7},{%8,%9},{%0,%1,%2,%3};"
        : "+f"(c[0]), "+f"(c[1]), "+f"(c[2]), "+f"(c[3])
        : "r"(a[0]), "r"(a[1]), "r"(a[2]), "r"(a[3]), "r"(b0), "r"(b1));
}

// ---------------------------------------------------------------------------
// GEMM via tensor cores: C[M,N] = A[M,K] @ W[K,N] + bias
// Block 256 thr (8 warps, 2x4), block tile 128x128, k-step 32, warp 64x32.
// MODE 0: A = x, epilogue scatters q(scaled)/k/v. MODE 1: A = g_att -> out.
// Static SMEM: 35840 B (legal).
// ---------------------------------------------------------------------------
template <int MODE>
__global__ __launch_bounds__(256)
void gemm_mma(const float* __restrict__ A, const float* __restrict__ W,
              const float* __restrict__ bias, float* __restrict__ out,
              int M, int N, int K)
{
    __shared__ unsigned As[128][36];   // stride 36: conflict-free A-frag LDS
    __shared__ unsigned Bs[32][136];   // stride 136: conflict-free B-frag LDS

    const int tid = threadIdx.x;
    const int lane = tid & 31, w = tid >> 5;
    const int g = lane >> 2, t4 = lane & 3;
    const int wm = w >> 2, wn = w & 3;              // 2 (M) x 4 (N)
    const int row0 = blockIdx.y * 128, n0 = blockIdx.x * 128;

    const float* Ap = (MODE == 0) ? A : (const float*)g_att;

    float C[4][4][4];
#pragma unroll
    for (int mt = 0; mt < 4; mt++)
#pragma unroll
        for (int nt = 0; nt < 4; nt++)
#pragma unroll
            for (int i = 0; i < 4; i++) C[mt][nt][i] = 0.f;

    for (int kk = 0; kk < K; kk += 32) {
#pragma unroll
        for (int i = 0; i < 4; i++) {               // A tile 128x32
            int e = tid + 256 * i;
            int r = e >> 3, c = (e & 7) * 4;
            float4 v = *(const float4*)&Ap[(size_t)(row0 + r) * K + kk + c];
            uint4 u = { f2tf(v.x), f2tf(v.y), f2tf(v.z), f2tf(v.w) };
            *(uint4*)&As[r][c] = u;
        }
#pragma unroll
        for (int i = 0; i < 4; i++) {               // W tile 32x128
            int e = tid + 256 * i;
            int r = e >> 5, c = (e & 31) * 4;
            float4 v = *(const float4*)&W[(size_t)(kk + r) * N + n0 + c];
            uint4 u = { f2tf(v.x), f2tf(v.y), f2tf(v.z), f2tf(v.w) };
            *(uint4*)&Bs[r][c] = u;
        }
        __syncthreads();

#pragma unroll
        for (int ks = 0; ks < 4; ks++) {
            unsigned a[4][4];
#pragma unroll
            for (int mt = 0; mt < 4; mt++) {
                int r = wm * 64 + mt * 16 + g, kc = ks * 8 + t4;
                a[mt][0] = As[r][kc];     a[mt][1] = As[r + 8][kc];
                a[mt][2] = As[r][kc + 4]; a[mt][3] = As[r + 8][kc + 4];
            }
#pragma unroll
            for (int nt = 0; nt < 4; nt++) {
                int nc = wn * 32 + nt * 8 + g, kc = ks * 8 + t4;
                unsigned b0 = Bs[kc][nc], b1 = Bs[kc + 4][nc];
#pragma unroll
                for (int mt = 0; mt < 4; mt++) mma8(C[mt][nt], a[mt], b0, b1);
            }
        }
        __syncthreads();
    }

    // epilogue
#pragma unroll
    for (int mt = 0; mt < 4; mt++) {
#pragma unroll
        for (int nt = 0; nt < 4; nt++) {
            int m = row0 + wm * 64 + mt * 16 + g;
            int n = n0 + wn * 32 + nt * 8 + 2 * t4;
#pragma unroll
            for (int half = 0; half < 2; half++) {
                int mm = m + half * 8;
#pragma unroll
                for (int dc = 0; dc < 2; dc++) {
                    int nn = n + dc;
                    float v = C[mt][nt][half * 2 + dc] + bias[nn];
                    if (MODE == 0) {
                        int which = nn / Dc;
                        int rr = nn - which * Dc;
                        int h = rr >> 6, hd = rr & 63;
                        int b = mm >> 11, s = mm & 2047;
                        int idx = ((b * Hc + h) * Sc + s) * HDc + hd;
                        if (which == 0)      g_q[idx] = v * QSCALE;
                        else if (which == 1) g_k[idx] = v;
                        else                 g_v[idx] = v;
                    } else {
                        out[(size_t)mm * N + nn] = v;
                    }
                }
            }
        }
    }
}

// ---------------------------------------------------------------------------
// Flash attention with tensor-core QK^T and PV, online softmax in registers.
// Block 128 thr (4 warps). Q tile 64 rows; warp owns 16 rows x full width.
// KV tiles of 64 keys. grid: (S/64, B*H).
// DYNAMIC SMEM: 76800 B (Qs/Ks/Ps stride 76, Vs stride 72).
// ---------------------------------------------------------------------------
#define ATTN_SMEM_WORDS (3 * 64 * 76 + 64 * 72)
#define ATTN_SMEM_BYTES (ATTN_SMEM_WORDS * 4)

__global__ __launch_bounds__(128)
void attn_mma()
{
    extern __shared__ unsigned dsm[];
    unsigned (*Qs)[76] = (unsigned(*)[76])(dsm);
    unsigned (*Ks)[76] = (unsigned(*)[76])(dsm + 64 * 76);
    unsigned (*Ps)[76] = (unsigned(*)[76])(dsm + 2 * 64 * 76);
    unsigned (*Vs)[72] = (unsigned(*)[72])(dsm + 3 * 64 * 76);

    const int tid = threadIdx.x;
    const int lane = tid & 31, w = tid >> 5;
    const int g = lane >> 2, t4 = lane & 3;
    const int bh = blockIdx.y, q0 = blockIdx.x * 64;
    const int b = bh / Hc, h = bh - b * Hc;

    const float* qb = g_q + ((size_t)bh * Sc + q0) * HDc;
    const float* kb = g_k + (size_t)bh * Sc * HDc;
    const float* vb = g_v + (size_t)bh * Sc * HDc;

    // load Q tile (pre-scaled), cvt to tf32
#pragma unroll
    for (int i = 0; i < 8; i++) {
        int e = tid + 128 * i;
        int r = e >> 4, c = (e & 15) * 4;
        float4 v = *(const float4*)&qb[(size_t)r * 64 + c];
        uint4 u = { f2tf(v.x), f2tf(v.y), f2tf(v.z), f2tf(v.w) };
        *(uint4*)&Qs[r][c] = u;
    }

    float O[8][4];
#pragma unroll
    for (int nt = 0; nt < 8; nt++)
#pragma unroll
        for (int i = 0; i < 4; i++) O[nt][i] = 0.f;
    float m_lo = -1e30f, m_hi = -1e30f, l_lo = 0.f, l_hi = 0.f;

    for (int kt = 0; kt < Sc; kt += 64) {
        // load K & V tiles
#pragma unroll
        for (int i = 0; i < 8; i++) {
            int e = tid + 128 * i;
            int r = e >> 4, c = (e & 15) * 4;
            float4 kv = *(const float4*)&kb[(size_t)(kt + r) * 64 + c];
            uint4 uk = { f2tf(kv.x), f2tf(kv.y), f2tf(kv.z), f2tf(kv.w) };
            *(uint4*)&Ks[r][c] = uk;
            float4 vv = *(const float4*)&vb[(size_t)(kt + r) * 64 + c];
            uint4 uv = { f2tf(vv.x), f2tf(vv.y), f2tf(vv.z), f2tf(vv.w) };
            *(uint4*)&Vs[r][c] = uv;
        }
        __syncthreads();

        // -------- S = Q @ K^T  (warp: 16 rows x 64 keys) --------
        unsigned aq[8][4];
#pragma unroll
        for (int ks = 0; ks < 8; ks++) {
            int r = w * 16 + g, kc = ks * 8 + t4;
            aq[ks][0] = Qs[r][kc];     aq[ks][1] = Qs[r + 8][kc];
            aq[ks][2] = Qs[r][kc + 4]; aq[ks][3] = Qs[r + 8][kc + 4];
        }
        float S[8][4];
#pragma unroll
        for (int nt = 0; nt < 8; nt++)
#pragma unroll
            for (int i = 0; i < 4; i++) S[nt][i] = 0.f;
#pragma unroll
        for (int ks = 0; ks < 8; ks++)
#pragma unroll
            for (int nt = 0; nt < 8; nt++) {
                unsigned b0 = Ks[nt * 8 + g][ks * 8 + t4];
                unsigned b1 = Ks[nt * 8 + g][ks * 8 + 4 + t4];
                mma8(S[nt], aq[ks], b0, b1);
            }

        // -------- online softmax (per-row in registers) --------
        float mx0 = -1e30f, mx1 = -1e30f;
#pragma unroll
        for (int nt = 0; nt < 8; nt++) {
            mx0 = fmaxf(mx0, fmaxf(S[nt][0], S[nt][1]));
            mx1 = fmaxf(mx1, fmaxf(S[nt][2], S[nt][3]));
        }
        mx0 = fmaxf(mx0, __shfl_xor_sync(0xffffffffu, mx0, 1));
        mx0 = fmaxf(mx0, __shfl_xor_sync(0xffffffffu, mx0, 2));
        mx1 = fmaxf(mx1, __shfl_xor_sync(0xffffffffu, mx1, 1));
        mx1 = fmaxf(mx1, __shfl_xor_sync(0xffffffffu, mx1, 2));

        float nm0 = fmaxf(m_lo, mx0), nm1 = fmaxf(m_hi, mx1);
        float al0 = __expf(m_lo - nm0), al1 = __expf(m_hi - nm1);
        m_lo = nm0; m_hi = nm1;

        float s0 = 0.f, s1 = 0.f;
#pragma unroll
        for (int nt = 0; nt < 8; nt++) {
            float p0 = __expf(S[nt][0] - nm0);
            float p1 = __expf(S[nt][1] - nm0);
            float p2 = __expf(S[nt][2] - nm1);
            float p3 = __expf(S[nt][3] - nm1);
            S[nt][0] = p0; S[nt][1] = p1; S[nt][2] = p2; S[nt][3] = p3;
            s0 += p0 + p1; s1 += p2 + p3;
        }
        s0 += __shfl_xor_sync(0xffffffffu, s0, 1);
        s0 += __shfl_xor_sync(0xffffffffu, s0, 2);
        s1 += __shfl_xor_sync(0xffffffffu, s1, 1);
        s1 += __shfl_xor_sync(0xffffffffu, s1, 2);
        l_lo = l_lo * al0 + s0;
        l_hi = l_hi * al1 + s1;

        // rescale O, store P (tf32) to SMEM (warp-private rows)
#pragma unroll
        for (int nt = 0; nt < 8; nt++) {
            O[nt][0] *= al0; O[nt][1] *= al0;
            O[nt][2] *= al1; O[nt][3] *= al1;
            int r = w * 16 + g, c = nt * 8 + 2 * t4;
            Ps[r][c]     = f2tf(S[nt][0]);
            Ps[r][c + 1] = f2tf(S[nt][1]);
            Ps[r + 8][c]     = f2tf(S[nt][2]);
            Ps[r + 8][c + 1] = f2tf(S[nt][3]);
        }
        __syncwarp();

        // -------- O += P @ V --------
        unsigned ap[8][4];
#pragma unroll
        for (int ks = 0; ks < 8; ks++) {
            int r = w * 16 + g, kc = ks * 8 + t4;
            ap[ks][0] = Ps[r][kc];     ap[ks][1] = Ps[r + 8][kc];
            ap[ks][2] = Ps[r][kc + 4]; ap[ks][3] = Ps[r + 8][kc + 4];
        }
#pragma unroll
        for (int ks = 0; ks < 8; ks++)
#pragma unroll
            for (int nt = 0; nt < 8; nt++) {
                unsigned b0 = Vs[ks * 8 + t4][nt * 8 + g];
                unsigned b1 = Vs[ks * 8 + 4 + t4][nt * 8 + g];
                mma8(O[nt], ap[ks], b0, b1);
            }
        __syncthreads();
    }

    // write normalized output to g_att [B,S,D]
    float inv0 = 1.f / l_lo, inv1 = 1.f / l_hi;
    float* ob = g_att + ((size_t)(b * Sc + q0)) * Dc + h * HDc;
#pragma unroll
    for (int nt = 0; nt < 8; nt++) {
        int r = w * 16 + g, c = nt * 8 + 2 * t4;
        float2 v0 = { O[nt][0] * inv0, O[nt][1] * inv0 };
        *(float2*)&ob[(size_t)r * Dc + c] = v0;
        float2 v1 = { O[nt][2] * inv1, O[nt][3] * inv1 };
        *(float2*)&ob[(size_t)(r + 8) * Dc + c] = v1;
    }
}

// ---------------------------------------------------------------------------
extern "C" void kernel_launch(void* const* d_in, const int* in_sizes, int n_in,
                              void* d_out, int out_size)
{
    const float* x      = (const float*)d_in[0];   // [B,S,D]
    const float* w_qkv  = (const float*)d_in[1];   // [D,3D]
    const float* b_qkv  = (const float*)d_in[2];   // [3D]
    const float* w_proj = (const float*)d_in[3];   // [D,D]
    const float* b_proj = (const float*)d_in[4];   // [D]
    float* out = (float*)d_out;                    // [B,S,D]

    const int M = Bc * Sc;  // 4096

    static bool attr_set = false;
    if (!attr_set) {
        cudaFuncSetAttribute(attn_mma, cudaFuncAttributeMaxDynamicSharedMemorySize,
                             ATTN_SMEM_BYTES);
        attr_set = true;
    }

    dim3 gq(3 * Dc / 128, M / 128);  // (18, 32)
    gemm_mma<0><<<gq, 256>>>(x, w_qkv, b_qkv, nullptr, M, 3 * Dc, Dc);

    dim3 ga(Sc / 64, Bc * Hc);       // (32, 24)
    attn_mma<<<ga, 128, ATTN_SMEM_BYTES>>>();

    dim3 gp(Dc / 128, M / 128);      // (6, 32)
    gemm_mma<1><<<gp, 256>>>(nullptr, w_proj, b_proj, out, M, Dc, Dc);
}

// round 5
// speedup vs baseline: 6.7911x; 1.8519x over previous
#include <cuda_runtime.h>
#include <cuda_fp16.h>

#define Bc 2
#define Sc 2048
#define Dc 768
#define Hc 12
#define HDc 64
#define QSCALE 0.125f   // 64^-0.5

// Scratch (allocation-free). q/k/v stored fp16 in [B,H,S,HD]; attn out fp32.
__device__ __half g_q[Bc * Hc * Sc * HDc];
__device__ __half g_k[Bc * Hc * Sc * HDc];
__device__ __half g_v[Bc * Hc * Sc * HDc];
__device__ float  g_att[Bc * Sc * Dc];

// ---------------------------------------------------------------------------
// helpers
// ---------------------------------------------------------------------------
__device__ __forceinline__ unsigned pack2(float lo, float hi) {
    __half2 h = __floats2half2_rn(lo, hi);
    return *(unsigned*)&h;
}
__device__ __forceinline__ unsigned sptr(const void* p) {
    return (unsigned)__cvta_generic_to_shared(p);
}
// D(16x8) += A(16x16) @ B(16x8), fp16 in, fp32 accum
__device__ __forceinline__ void mma16(float c[4], const unsigned a[4],
                                      unsigned b0, unsigned b1) {
    asm volatile(
        "mma.sync.aligned.m16n8k16.row.col.f32.f16.f16.f32 "
        "{%0,%1,%2,%3},{%4,%5,%6,%7},{%8,%9},{%0,%1,%2,%3};"
        : "+f"(c[0]), "+f"(c[1]), "+f"(c[2]), "+f"(c[3])
        : "r"(a[0]), "r"(a[1]), "r"(a[2]), "r"(a[3]), "r"(b0), "r"(b1));
}
__device__ __forceinline__ void ldm_x4(unsigned r[4], const void* p) {
    unsigned a = sptr(p);
    asm volatile("ldmatrix.sync.aligned.m8n8.x4.shared.b16 {%0,%1,%2,%3}, [%4];"
                 : "=r"(r[0]), "=r"(r[1]), "=r"(r[2]), "=r"(r[3]) : "r"(a));
}
__device__ __forceinline__ void ldm_x4_t(unsigned r[4], const void* p) {
    unsigned a = sptr(p);
    asm volatile("ldmatrix.sync.aligned.m8n8.x4.trans.shared.b16 {%0,%1,%2,%3}, [%4];"
                 : "=r"(r[0]), "=r"(r[1]), "=r"(r[2]), "=r"(r[3]) : "r"(a));
}

// ---------------------------------------------------------------------------
// fp16-MMA GEMM: C[M,N] = A[M,K] @ W[K,N] + bias.  Block 256 thr (8 warps 2x4),
// tile 128x128, k-step 32 (two k16 subs), warp 64x32, double-buffered SMEM with
// register prefetch (one __syncthreads per k-step).  Static SMEM 37,888 B.
// MODE 0: A = x, scatter epilogue -> g_q(scaled)/g_k/g_v (fp16).
// MODE 1: A = g_att (f32), write out + bias.
// ---------------------------------------------------------------------------
template <int MODE>
__global__ __launch_bounds__(256)
void gemm_mma(const float* __restrict__ A, const float* __restrict__ W,
              const float* __restrict__ bias, float* __restrict__ out,
              int M, int N, int K)
{
    __shared__ __align__(16) __half As[2][128][40];
    __shared__ __align__(16) __half Bs[2][32][136];

    const int tid = threadIdx.x;
    const int lane = tid & 31, w = tid >> 5;
    const int g = lane >> 2, t4 = lane & 3;
    const int wm = w >> 2, wn = w & 3;
    const int row0 = blockIdx.y * 128, n0 = blockIdx.x * 128;

    const float* Ap = (MODE == 0) ? A : (const float*)g_att;

    float C[4][4][4];
#pragma unroll
    for (int mt = 0; mt < 4; mt++)
#pragma unroll
        for (int nt = 0; nt < 4; nt++)
#pragma unroll
            for (int i = 0; i < 4; i++) C[mt][nt][i] = 0.f;

    float4 pa[4], pb[4];
    // prologue: load + stage k-chunk 0
#pragma unroll
    for (int i = 0; i < 4; i++) {
        int e = tid + 256 * i; int r = e >> 3, c = (e & 7) * 4;
        pa[i] = *(const float4*)&Ap[(size_t)(row0 + r) * K + c];
    }
#pragma unroll
    for (int i = 0; i < 4; i++) {
        int e = tid + 256 * i; int r = e >> 5, c = (e & 31) * 4;
        pb[i] = *(const float4*)&W[(size_t)r * N + n0 + c];
    }
#pragma unroll
    for (int i = 0; i < 4; i++) {
        int e = tid + 256 * i; int r = e >> 3, c = (e & 7) * 4;
        uint2 u;
        u.x = pack2(pa[i].x, pa[i].y);
        u.y = pack2(pa[i].z, pa[i].w);
        *(uint2*)&As[0][r][c] = u;
    }
#pragma unroll
    for (int i = 0; i < 4; i++) {
        int e = tid + 256 * i; int r = e >> 5, c = (e & 31) * 4;
        uint2 u;
        u.x = pack2(pb[i].x, pb[i].y);
        u.y = pack2(pb[i].z, pb[i].w);
        *(uint2*)&Bs[0][r][c] = u;
    }
    __syncthreads();

    const int NIT = K / 32;
    for (int it = 0; it < NIT; it++) {
        const int buf = it & 1;
        if (it + 1 < NIT) {
            int kk = (it + 1) * 32;
#pragma unroll
            for (int i = 0; i < 4; i++) {
                int e = tid + 256 * i; int r = e >> 3, c = (e & 7) * 4;
                pa[i] = *(const float4*)&Ap[(size_t)(row0 + r) * K + kk + c];
            }
#pragma unroll
            for (int i = 0; i < 4; i++) {
                int e = tid + 256 * i; int r = e >> 5, c = (e & 31) * 4;
                pb[i] = *(const float4*)&W[(size_t)(kk + r) * N + n0 + c];
            }
        }

#pragma unroll
        for (int sub = 0; sub < 2; sub++) {
            unsigned a[4][4], bfr[2][4];
            const int arow = wm * 64 + (lane & 7) + (lane & 8);
            const int acol = sub * 16 + ((lane & 16) >> 1);
#pragma unroll
            for (int mt = 0; mt < 4; mt++)
                ldm_x4(a[mt], &As[buf][arow + mt * 16][acol]);
            const int brow = sub * 16 + (lane & 7) + (lane & 8);
#pragma unroll
            for (int nh = 0; nh < 2; nh++)
                ldm_x4_t(bfr[nh], &Bs[buf][brow][wn * 32 + nh * 16 + ((lane & 16) >> 1)]);
#pragma unroll
            for (int mt = 0; mt < 4; mt++)
#pragma unroll
                for (int nt = 0; nt < 4; nt++)
                    mma16(C[mt][nt], a[mt],
                          bfr[nt >> 1][(nt & 1) * 2], bfr[nt >> 1][(nt & 1) * 2 + 1]);
        }

        if (it + 1 < NIT) {
#pragma unroll
            for (int i = 0; i < 4; i++) {
                int e = tid + 256 * i; int r = e >> 3, c = (e & 7) * 4;
                uint2 u;
                u.x = pack2(pa[i].x, pa[i].y);
                u.y = pack2(pa[i].z, pa[i].w);
                *(uint2*)&As[buf ^ 1][r][c] = u;
            }
#pragma unroll
            for (int i = 0; i < 4; i++) {
                int e = tid + 256 * i; int r = e >> 5, c = (e & 31) * 4;
                uint2 u;
                u.x = pack2(pb[i].x, pb[i].y);
                u.y = pack2(pb[i].z, pb[i].w);
                *(uint2*)&Bs[buf ^ 1][r][c] = u;
            }
        }
        __syncthreads();
    }

    // epilogue
#pragma unroll
    for (int mt = 0; mt < 4; mt++) {
#pragma unroll
        for (int nt = 0; nt < 4; nt++) {
            int m = row0 + wm * 64 + mt * 16 + g;
            int n = n0 + wn * 32 + nt * 8 + 2 * t4;
#pragma unroll
            for (int half = 0; half < 2; half++) {
                int mm = m + half * 8;
#pragma unroll
                for (int dc = 0; dc < 2; dc++) {
                    int nn = n + dc;
                    float v = C[mt][nt][half * 2 + dc] + bias[nn];
                    if (MODE == 0) {
                        int which = nn / Dc;
                        int rr = nn - which * Dc;
                        int h = rr >> 6, hd = rr & 63;
                        int b = mm >> 11, s = mm & 2047;
                        int idx = ((b * Hc + h) * Sc + s) * HDc + hd;
                        if (which == 0)      g_q[idx] = __float2half(v * QSCALE);
                        else if (which == 1) g_k[idx] = __float2half(v);
                        else                 g_v[idx] = __float2half(v);
                    } else {
                        out[(size_t)mm * N + nn] = v;
                    }
                }
            }
        }
    }
}

// ---------------------------------------------------------------------------
// Flash attention, fp16 MMA. Block 128 thr (4 warps), Q tile 64 rows (warp=16),
// KV tile 64 keys. Q fragments hoisted; P never leaves registers (PV A-frag is
// packed S pairs). grid: (S/64, B*H).  Static SMEM 27,648 B.
// ---------------------------------------------------------------------------
__global__ __launch_bounds__(128)
void attn_mma()
{
    __shared__ __align__(16) __half Qs[64][72];
    __shared__ __align__(16) __half Ks[64][72];
    __shared__ __align__(16) __half Vs[64][72];

    const int tid = threadIdx.x;
    const int lane = tid & 31, w = tid >> 5;
    const int g = lane >> 2, t4 = lane & 3;
    const int bh = blockIdx.y, q0 = blockIdx.x * 64;
    const int b = bh / Hc, h = bh - b * Hc;

    const __half* qb = g_q + ((size_t)bh * Sc + q0) * HDc;
    const __half* kb = g_k + (size_t)bh * Sc * HDc;
    const __half* vb = g_v + (size_t)bh * Sc * HDc;

    // load Q tile (fp16, pre-scaled)
#pragma unroll
    for (int i = 0; i < 4; i++) {
        int u = tid + 128 * i; int r = u >> 3, c = (u & 7) * 8;
        *(uint4*)&Qs[r][c] = *(const uint4*)&qb[(size_t)r * 64 + c];
    }
    __syncthreads();

    // hoist Q fragments (once per block)
    unsigned aq[4][4];
    {
        int r = w * 16 + g;
#pragma unroll
        for (int ks = 0; ks < 4; ks++) {
            aq[ks][0] = *(const unsigned*)&Qs[r][ks * 16 + 2 * t4];
            aq[ks][1] = *(const unsigned*)&Qs[r + 8][ks * 16 + 2 * t4];
            aq[ks][2] = *(const unsigned*)&Qs[r][ks * 16 + 8 + 2 * t4];
            aq[ks][3] = *(const unsigned*)&Qs[r + 8][ks * 16 + 8 + 2 * t4];
        }
    }

    float O[8][4];
#pragma unroll
    for (int nt = 0; nt < 8; nt++)
#pragma unroll
        for (int i = 0; i < 4; i++) O[nt][i] = 0.f;
    float m_lo = -1e30f, m_hi = -1e30f, l_lo = 0.f, l_hi = 0.f;

    for (int kt = 0; kt < Sc; kt += 64) {
#pragma unroll
        for (int i = 0; i < 4; i++) {
            int u = tid + 128 * i; int r = u >> 3, c = (u & 7) * 8;
            *(uint4*)&Ks[r][c] = *(const uint4*)&kb[(size_t)(kt + r) * 64 + c];
            *(uint4*)&Vs[r][c] = *(const uint4*)&vb[(size_t)(kt + r) * 64 + c];
        }
        __syncthreads();

        // -------- S = Q @ K^T --------
        float S[8][4];
#pragma unroll
        for (int nt = 0; nt < 8; nt++)
#pragma unroll
            for (int i = 0; i < 4; i++) S[nt][i] = 0.f;
#pragma unroll
        for (int ks = 0; ks < 4; ks++) {
            unsigned bk[4][4];
#pragma unroll
            for (int nh = 0; nh < 4; nh++) {
                int krow = nh * 16 + (lane & 7) + ((lane & 16) >> 1);
                int kcol = ks * 16 + (lane & 8);
                ldm_x4(bk[nh], &Ks[krow][kcol]);
            }
#pragma unroll
            for (int nt = 0; nt < 8; nt++)
                mma16(S[nt], aq[ks],
                      bk[nt >> 1][(nt & 1) * 2], bk[nt >> 1][(nt & 1) * 2 + 1]);
        }

        // -------- online softmax --------
        float mx0 = -1e30f, mx1 = -1e30f;
#pragma unroll
        for (int nt = 0; nt < 8; nt++) {
            mx0 = fmaxf(mx0, fmaxf(S[nt][0], S[nt][1]));
            mx1 = fmaxf(mx1, fmaxf(S[nt][2], S[nt][3]));
        }
        mx0 = fmaxf(mx0, __shfl_xor_sync(0xffffffffu, mx0, 1));
        mx0 = fmaxf(mx0, __shfl_xor_sync(0xffffffffu, mx0, 2));
        mx1 = fmaxf(mx1, __shfl_xor_sync(0xffffffffu, mx1, 1));
        mx1 = fmaxf(mx1, __shfl_xor_sync(0xffffffffu, mx1, 2));

        float nm0 = fmaxf(m_lo, mx0), nm1 = fmaxf(m_hi, mx1);
        float al0 = __expf(m_lo - nm0), al1 = __expf(m_hi - nm1);
        m_lo = nm0; m_hi = nm1;

        float s0 = 0.f, s1 = 0.f;
#pragma unroll
        for (int nt = 0; nt < 8; nt++) {
            float p0 = __expf(S[nt][0] - nm0);
            float p1 = __expf(S[nt][1] - nm0);
            float p2 = __expf(S[nt][2] - nm1);
            float p3 = __expf(S[nt][3] - nm1);
            S[nt][0] = p0; S[nt][1] = p1; S[nt][2] = p2; S[nt][3] = p3;
            s0 += p0 + p1; s1 += p2 + p3;
        }
        s0 += __shfl_xor_sync(0xffffffffu, s0, 1);
        s0 += __shfl_xor_sync(0xffffffffu, s0, 2);
        s1 += __shfl_xor_sync(0xffffffffu, s1, 1);
        s1 += __shfl_xor_sync(0xffffffffu, s1, 2);
        l_lo = l_lo * al0 + s0;
        l_hi = l_hi * al1 + s1;

        // rescale O; pack P into PV A-fragments directly from registers
#pragma unroll
        for (int nt = 0; nt < 8; nt++) {
            O[nt][0] *= al0; O[nt][1] *= al0;
            O[nt][2] *= al1; O[nt][3] *= al1;
        }
        unsigned ap[4][4];
#pragma unroll
        for (int ks = 0; ks < 4; ks++) {
            ap[ks][0] = pack2(S[2 * ks][0], S[2 * ks][1]);
            ap[ks][1] = pack2(S[2 * ks][2], S[2 * ks][3]);
            ap[ks][2] = pack2(S[2 * ks + 1][0], S[2 * ks + 1][1]);
            ap[ks][3] = pack2(S[2 * ks + 1][2], S[2 * ks + 1][3]);
        }

        // -------- O += P @ V --------
#pragma unroll
        for (int ks = 0; ks < 4; ks++) {
            unsigned bv[4][4];
#pragma unroll
            for (int nh = 0; nh < 4; nh++) {
                int vrow = ks * 16 + (lane & 7) + (lane & 8);
                int vcol = nh * 16 + ((lane & 16) >> 1);
                ldm_x4_t(bv[nh], &Vs[vrow][vcol]);
            }
#pragma unroll
            for (int nt = 0; nt < 8; nt++)
                mma16(O[nt], ap[ks],
                      bv[nt >> 1][(nt & 1) * 2], bv[nt >> 1][(nt & 1) * 2 + 1]);
        }
        __syncthreads();
    }

    // write normalized output to g_att [B,S,D] (fp32)
    float inv0 = 1.f / l_lo, inv1 = 1.f / l_hi;
    float* ob = g_att + ((size_t)(b * Sc + q0)) * Dc + h * HDc;
#pragma unroll
    for (int nt = 0; nt < 8; nt++) {
        int r = w * 16 + g, c = nt * 8 + 2 * t4;
        float2 v0;
        v0.x = O[nt][0] * inv0; v0.y = O[nt][1] * inv0;
        *(float2*)&ob[(size_t)r * Dc + c] = v0;
        float2 v1;
        v1.x = O[nt][2] * inv1; v1.y = O[nt][3] * inv1;
        *(float2*)&ob[(size_t)(r + 8) * Dc + c] = v1;
    }
}

// ---------------------------------------------------------------------------
extern "C" void kernel_launch(void* const* d_in, const int* in_sizes, int n_in,
                              void* d_out, int out_size)
{
    (void)in_sizes; (void)n_in; (void)out_size;
    const float* x      = (const float*)d_in[0];   // [B,S,D]
    const float* w_qkv  = (const float*)d_in[1];   // [D,3D]
    const float* b_qkv  = (const float*)d_in[2];   // [3D]
    const float* w_proj = (const float*)d_in[3];   // [D,D]
    const float* b_proj = (const float*)d_in[4];   // [D]
    float* out = (float*)d_out;                    // [B,S,D]

    const int M = Bc * Sc;  // 4096

    dim3 gq(3 * Dc / 128, M / 128);  // (18, 32)
    gemm_mma<0><<<gq, 256>>>(x, w_qkv, b_qkv, nullptr, M, 3 * Dc, Dc);

    dim3 ga(Sc / 64, Bc * Hc);       // (32, 24)
    attn_mma<<<ga, 128>>>();

    dim3 gp(Dc / 128, M / 128);      // (6, 32)
    gemm_mma<1><<<gp, 256>>>(nullptr, w_proj, b_proj, out, M, Dc, Dc);
}

// round 8
// speedup vs baseline: 7.3631x; 1.0842x over previous
#include <cuda_runtime.h>
#include <cuda_fp16.h>

#define Bc 2
#define Sc 2048
#define Dc 768
#define Hc 12
#define HDc 64
#define QSCALE 0.125f   // 64^-0.5

// Scratch (allocation-free)
__device__ __half g_xh[Bc * Sc * Dc];          // x in fp16
__device__ __half g_wqkv[Dc * 3 * Dc];         // w_qkv in fp16
__device__ __half g_wproj[Dc * Dc];            // w_proj in fp16
__device__ __half g_q[Bc * Hc * Sc * HDc];
__device__ __half g_k[Bc * Hc * Sc * HDc];
__device__ __half g_v[Bc * Hc * Sc * HDc];
__device__ __half g_att[Bc * Sc * Dc];

// ---------------------------------------------------------------------------
// helpers
// ---------------------------------------------------------------------------
__device__ __forceinline__ unsigned pack2(float lo, float hi) {
    __half2 h = __floats2half2_rn(lo, hi);
    return *(unsigned*)&h;
}
__device__ __forceinline__ unsigned sptr(const void* p) {
    return (unsigned)__cvta_generic_to_shared(p);
}
__device__ __forceinline__ void mma16(float c[4], const unsigned a[4],
                                      unsigned b0, unsigned b1) {
    asm volatile(
        "mma.sync.aligned.m16n8k16.row.col.f32.f16.f16.f32 "
        "{%0,%1,%2,%3},{%4,%5,%6,%7},{%8,%9},{%0,%1,%2,%3};"
        : "+f"(c[0]), "+f"(c[1]), "+f"(c[2]), "+f"(c[3])
        : "r"(a[0]), "r"(a[1]), "r"(a[2]), "r"(a[3]), "r"(b0), "r"(b1));
}
__device__ __forceinline__ void ldm_x4(unsigned r[4], const void* p) {
    unsigned a = sptr(p);
    asm volatile("ldmatrix.sync.aligned.m8n8.x4.shared.b16 {%0,%1,%2,%3}, [%4];"
                 : "=r"(r[0]), "=r"(r[1]), "=r"(r[2]), "=r"(r[3]) : "r"(a));
}
__device__ __forceinline__ void ldm_x4_t(unsigned r[4], const void* p) {
    unsigned a = sptr(p);
    asm volatile("ldmatrix.sync.aligned.m8n8.x4.trans.shared.b16 {%0,%1,%2,%3}, [%4];"
                 : "=r"(r[0]), "=r"(r[1]), "=r"(r[2]), "=r"(r[3]) : "r"(a));
}
__device__ __forceinline__ void cpa16(void* s, const void* g) {
    asm volatile("cp.async.cg.shared.global [%0], [%1], 16;"
                 :: "r"(sptr(s)), "l"(g));
}
__device__ __forceinline__ void cp_commit() {
    asm volatile("cp.async.commit_group;");
}
template <int N> __device__ __forceinline__ void cp_wait() {
    asm volatile("cp.async.wait_group %0;" :: "n"(N));
}

// ---------------------------------------------------------------------------
// fp32 -> fp16 elementwise convert (8 elems/thread)
// ---------------------------------------------------------------------------
__global__ __launch_bounds__(256)
void cvt_kernel(const float* __restrict__ in, __half* __restrict__ out, int n)
{
    int i = (blockIdx.x * 256 + threadIdx.x) * 8;
    if (i >= n) return;
    float4 a = *(const float4*)(in + i);
    float4 b = *(const float4*)(in + i + 4);
    uint4 u;
    u.x = pack2(a.x, a.y); u.y = pack2(a.z, a.w);
    u.z = pack2(b.x, b.y); u.w = pack2(b.z, b.w);
    *(uint4*)(out + i) = u;
}

// ---------------------------------------------------------------------------
// fp16 GEMM: C[M,N] = A[M,K] @ W[K,N] + bias. Both operands fp16 in gmem.
// Block 256 thr (8 warps 2x4), tile 128x128, k-step 32, cp.async double-buffer.
// A tile 128x32 halves = 512 x 16B chunks -> 2/thread.
// W tile  32x128 halves = 512 x 16B chunks -> 2/thread.
// MODE 0: scatter epilogue -> g_q(scaled)/g_k/g_v. MODE 1: out = C + bias (f32).
// ---------------------------------------------------------------------------
template <int MODE>
__global__ __launch_bounds__(256)
void gemm_mma(const __half* __restrict__ A, const __half* __restrict__ W,
              const float* __restrict__ bias, float* __restrict__ out,
              int M, int N, int K)
{
    __shared__ __align__(16) __half As[2][128][40];
    __shared__ __align__(16) __half Bs[2][32][136];

    const int tid = threadIdx.x;
    const int lane = tid & 31, w = tid >> 5;
    const int g = lane >> 2, t4 = lane & 3;
    const int wm = w >> 2, wn = w & 3;
    const int row0 = blockIdx.y * 128, n0 = blockIdx.x * 128;

    float C[4][4][4];
#pragma unroll
    for (int mt = 0; mt < 4; mt++)
#pragma unroll
        for (int nt = 0; nt < 4; nt++)
#pragma unroll
            for (int i = 0; i < 4; i++) C[mt][nt][i] = 0.f;

    // per-thread cp.async chunk coords
    // A: 512 chunks, 2/thread. rows 0..127, 4 chunks (32 halves) per row.
    const int ar0 = (tid + 0)   >> 2, ac0 = ((tid + 0)   & 3) * 8;
    const int ar1 = (tid + 256) >> 2, ac1 = ((tid + 256) & 3) * 8;
    // W: 512 chunks, 2/thread. rows 0..31, 16 chunks (128 halves) per row.
    const int wr0 = (tid + 0)   >> 4, wc0 = ((tid + 0)   & 15) * 8;
    const int wr1 = (tid + 256) >> 4, wc1 = ((tid + 256) & 15) * 8;

    const int NIT = K / 32;
    // prologue: issue k-chunk 0
    cpa16(&As[0][ar0][ac0], &A[(size_t)(row0 + ar0) * K + ac0]);
    cpa16(&As[0][ar1][ac1], &A[(size_t)(row0 + ar1) * K + ac1]);
    cpa16(&Bs[0][wr0][wc0], &W[(size_t)wr0 * N + n0 + wc0]);
    cpa16(&Bs[0][wr1][wc1], &W[(size_t)wr1 * N + n0 + wc1]);
    cp_commit();

    for (int it = 0; it < NIT; it++) {
        const int buf = it & 1;
        if (it + 1 < NIT) {
            int kk = (it + 1) * 32;
            cpa16(&As[buf ^ 1][ar0][ac0], &A[(size_t)(row0 + ar0) * K + kk + ac0]);
            cpa16(&As[buf ^ 1][ar1][ac1], &A[(size_t)(row0 + ar1) * K + kk + ac1]);
            cpa16(&Bs[buf ^ 1][wr0][wc0], &W[(size_t)(kk + wr0) * N + n0 + wc0]);
            cpa16(&Bs[buf ^ 1][wr1][wc1], &W[(size_t)(kk + wr1) * N + n0 + wc1]);
            cp_commit();
            cp_wait<1>();
        } else {
            cp_wait<0>();
        }
        __syncthreads();

#pragma unroll
        for (int sub = 0; sub < 2; sub++) {
            unsigned a[4][4], bfr[2][4];
            const int arow = wm * 64 + (lane & 7) + (lane & 8);
            const int acol = sub * 16 + ((lane & 16) >> 1);
#pragma unroll
            for (int mt = 0; mt < 4; mt++)
                ldm_x4(a[mt], &As[buf][arow + mt * 16][acol]);
            const int brow = sub * 16 + (lane & 7) + (lane & 8);
#pragma unroll
            for (int nh = 0; nh < 2; nh++)
                ldm_x4_t(bfr[nh], &Bs[buf][brow][wn * 32 + nh * 16 + ((lane & 16) >> 1)]);
#pragma unroll
            for (int mt = 0; mt < 4; mt++)
#pragma unroll
                for (int nt = 0; nt < 4; nt++)
                    mma16(C[mt][nt], a[mt],
                          bfr[nt >> 1][(nt & 1) * 2], bfr[nt >> 1][(nt & 1) * 2 + 1]);
        }
        __syncthreads();   // guard buf^1 before next iter's cp.async overwrite
    }

    // epilogue
#pragma unroll
    for (int mt = 0; mt < 4; mt++) {
#pragma unroll
        for (int nt = 0; nt < 4; nt++) {
            int m = row0 + wm * 64 + mt * 16 + g;
            int n = n0 + wn * 32 + nt * 8 + 2 * t4;
#pragma unroll
            for (int half = 0; half < 2; half++) {
                int mm = m + half * 8;
#pragma unroll
                for (int dc = 0; dc < 2; dc++) {
                    int nn = n + dc;
                    float v = C[mt][nt][half * 2 + dc] + bias[nn];
                    if (MODE == 0) {
                        int which = nn / Dc;
                        int rr = nn - which * Dc;
                        int h = rr >> 6, hd = rr & 63;
                        int b = mm >> 11, s = mm & 2047;
                        int idx = ((b * Hc + h) * Sc + s) * HDc + hd;
                        if (which == 0)      g_q[idx] = __float2half(v * QSCALE);
                        else if (which == 1) g_k[idx] = __float2half(v);
                        else                 g_v[idx] = __float2half(v);
                    } else {
                        out[(size_t)mm * N + nn] = v;
                    }
                }
            }
        }
    }
}

// ---------------------------------------------------------------------------
// Flash attention, fp16 MMA, cp.async double-buffered KV tiles.
// Block 128 thr (4 warps), Q tile 64 rows (warp=16), KV tile 64 keys.
// Static SMEM: Q 9216 + K/V 2x2x9216 = 46080 B.
// ---------------------------------------------------------------------------
__global__ __launch_bounds__(128)
void attn_mma()
{
    __shared__ __align__(16) __half Qs[64][72];
    __shared__ __align__(16) __half Ks[2][64][72];
    __shared__ __align__(16) __half Vs[2][64][72];

    const int tid = threadIdx.x;
    const int lane = tid & 31, w = tid >> 5;
    const int g = lane >> 2, t4 = lane & 3;
    const int bh = blockIdx.y, q0 = blockIdx.x * 64;
    const int b = bh / Hc, h = bh - b * Hc;

    const __half* qb = g_q + ((size_t)bh * Sc + q0) * HDc;
    const __half* kb = g_k + (size_t)bh * Sc * HDc;
    const __half* vb = g_v + (size_t)bh * Sc * HDc;

    // per-thread KV chunk coords: tile 64x64 halves = 512 chunks -> 4/thread
    int cr[4], cc[4];
#pragma unroll
    for (int i = 0; i < 4; i++) {
        int e = tid + 128 * i;
        cr[i] = e >> 3; cc[i] = (e & 7) * 8;
    }

    // load Q tile + issue KV tile 0
#pragma unroll
    for (int i = 0; i < 4; i++)
        *(uint4*)&Qs[cr[i]][cc[i]] = *(const uint4*)&qb[(size_t)cr[i] * 64 + cc[i]];
#pragma unroll
    for (int i = 0; i < 4; i++) {
        cpa16(&Ks[0][cr[i]][cc[i]], &kb[(size_t)cr[i] * 64 + cc[i]]);
        cpa16(&Vs[0][cr[i]][cc[i]], &vb[(size_t)cr[i] * 64 + cc[i]]);
    }
    cp_commit();
    __syncthreads();

    // hoist Q fragments
    unsigned aq[4][4];
    {
        int r = w * 16 + g;
#pragma unroll
        for (int ks = 0; ks < 4; ks++) {
            aq[ks][0] = *(const unsigned*)&Qs[r][ks * 16 + 2 * t4];
            aq[ks][1] = *(const unsigned*)&Qs[r + 8][ks * 16 + 2 * t4];
            aq[ks][2] = *(const unsigned*)&Qs[r][ks * 16 + 8 + 2 * t4];
            aq[ks][3] = *(const unsigned*)&Qs[r + 8][ks * 16 + 8 + 2 * t4];
        }
    }

    float O[8][4];
#pragma unroll
    for (int nt = 0; nt < 8; nt++)
#pragma unroll
        for (int i = 0; i < 4; i++) O[nt][i] = 0.f;
    float m_lo = -1e30f, m_hi = -1e30f, l_lo = 0.f, l_hi = 0.f;

    const int NT = Sc / 64;
    for (int t = 0; t < NT; t++) {
        const int buf = t & 1;
        if (t + 1 < NT) {
            size_t off = (size_t)(t + 1) * 64 * 64;
#pragma unroll
            for (int i = 0; i < 4; i++) {
                cpa16(&Ks[buf ^ 1][cr[i]][cc[i]], &kb[off + (size_t)cr[i] * 64 + cc[i]]);
                cpa16(&Vs[buf ^ 1][cr[i]][cc[i]], &vb[off + (size_t)cr[i] * 64 + cc[i]]);
            }
            cp_commit();
            cp_wait<1>();
        } else {
            cp_wait<0>();
        }
        __syncthreads();

        // -------- S = Q @ K^T --------
        float S[8][4];
#pragma unroll
        for (int nt = 0; nt < 8; nt++)
#pragma unroll
            for (int i = 0; i < 4; i++) S[nt][i] = 0.f;
#pragma unroll
        for (int ks = 0; ks < 4; ks++) {
            unsigned bk[4][4];
#pragma unroll
            for (int nh = 0; nh < 4; nh++) {
                int krow = nh * 16 + (lane & 7) + ((lane & 16) >> 1);
                int kcol = ks * 16 + (lane & 8);
                ldm_x4(bk[nh], &Ks[buf][krow][kcol]);
            }
#pragma unroll
            for (int nt = 0; nt < 8; nt++)
                mma16(S[nt], aq[ks],
                      bk[nt >> 1][(nt & 1) * 2], bk[nt >> 1][(nt & 1) * 2 + 1]);
        }

        // -------- online softmax --------
        float mx0 = -1e30f, mx1 = -1e30f;
#pragma unroll
        for (int nt = 0; nt < 8; nt++) {
            mx0 = fmaxf(mx0, fmaxf(S[nt][0], S[nt][1]));
            mx1 = fmaxf(mx1, fmaxf(S[nt][2], S[nt][3]));
        }
        mx0 = fmaxf(mx0, __shfl_xor_sync(0xffffffffu, mx0, 1));
        mx0 = fmaxf(mx0, __shfl_xor_sync(0xffffffffu, mx0, 2));
        mx1 = fmaxf(mx1, __shfl_xor_sync(0xffffffffu, mx1, 1));
        mx1 = fmaxf(mx1, __shfl_xor_sync(0xffffffffu, mx1, 2));

        float nm0 = fmaxf(m_lo, mx0), nm1 = fmaxf(m_hi, mx1);
        float al0 = __expf(m_lo - nm0), al1 = __expf(m_hi - nm1);
        m_lo = nm0; m_hi = nm1;

        float s0 = 0.f, s1 = 0.f;
#pragma unroll
        for (int nt = 0; nt < 8; nt++) {
            float p0 = __expf(S[nt][0] - nm0);
            float p1 = __expf(S[nt][1] - nm0);
            float p2 = __expf(S[nt][2] - nm1);
            float p3 = __expf(S[nt][3] - nm1);
            S[nt][0] = p0; S[nt][1] = p1; S[nt][2] = p2; S[nt][3] = p3;
            s0 += p0 + p1; s1 += p2 + p3;
        }
        s0 += __shfl_xor_sync(0xffffffffu, s0, 1);
        s0 += __shfl_xor_sync(0xffffffffu, s0, 2);
        s1 += __shfl_xor_sync(0xffffffffu, s1, 1);
        s1 += __shfl_xor_sync(0xffffffffu, s1, 2);
        l_lo = l_lo * al0 + s0;
        l_hi = l_hi * al1 + s1;

        // rescale O; pack P into PV A-fragments
#pragma unroll
        for (int nt = 0; nt < 8; nt++) {
            O[nt][0] *= al0; O[nt][1] *= al0;
            O[nt][2] *= al1; O[nt][3] *= al1;
        }
        unsigned ap[4][4];
#pragma unroll
        for (int ks = 0; ks < 4; ks++) {
            ap[ks][0] = pack2(S[2 * ks][0], S[2 * ks][1]);
            ap[ks][1] = pack2(S[2 * ks][2], S[2 * ks][3]);
            ap[ks][2] = pack2(S[2 * ks + 1][0], S[2 * ks + 1][1]);
            ap[ks][3] = pack2(S[2 * ks + 1][2], S[2 * ks + 1][3]);
        }

        // -------- O += P @ V --------
#pragma unroll
        for (int ks = 0; ks < 4; ks++) {
            unsigned bv[4][4];
#pragma unroll
            for (int nh = 0; nh < 4; nh++) {
                int vrow = ks * 16 + (lane & 7) + (lane & 8);
                int vcol = nh * 16 + ((lane & 16) >> 1);
                ldm_x4_t(bv[nh], &Vs[buf][vrow][vcol]);
            }
#pragma unroll
            for (int nt = 0; nt < 8; nt++)
                mma16(O[nt], ap[ks],
                      bv[nt >> 1][(nt & 1) * 2], bv[nt >> 1][(nt & 1) * 2 + 1]);
        }
        __syncthreads();   // guard buf^1 before next iter's cp.async overwrite
    }

    // write normalized output to g_att [B,S,D] (fp16)
    float inv0 = 1.f / l_lo, inv1 = 1.f / l_hi;
    __half* ob = g_att + ((size_t)(b * Sc + q0)) * Dc + h * HDc;
#pragma unroll
    for (int nt = 0; nt < 8; nt++) {
        int r = w * 16 + g, c = nt * 8 + 2 * t4;
        *(unsigned*)&ob[(size_t)r * Dc + c] = pack2(O[nt][0] * inv0, O[nt][1] * inv0);
        *(unsigned*)&ob[(size_t)(r + 8) * Dc + c] = pack2(O[nt][2] * inv1, O[nt][3] * inv1);
    }
}

// ---------------------------------------------------------------------------
extern "C" void kernel_launch(void* const* d_in, const int* in_sizes, int n_in,
                              void* d_out, int out_size)
{
    (void)in_sizes; (void)n_in; (void)out_size;
    const float* x      = (const float*)d_in[0];   // [B,S,D]
    const float* w_qkv  = (const float*)d_in[1];   // [D,3D]
    const float* b_qkv  = (const float*)d_in[2];   // [3D]
    const float* w_proj = (const float*)d_in[3];   // [D,D]
    const float* b_proj = (const float*)d_in[4];   // [D]
    float* out = (float*)d_out;                    // [B,S,D]

    const int M = Bc * Sc;  // 4096
    const int NX = Bc * Sc * Dc;         // 3,145,728
    const int NWQ = Dc * 3 * Dc;         // 1,769,472
    const int NWP = Dc * Dc;             // 589,824

    __half* xh;    cudaGetSymbolAddress((void**)&xh, g_xh);
    __half* wqh;   cudaGetSymbolAddress((void**)&wqh, g_wqkv);
    __half* wph;   cudaGetSymbolAddress((void**)&wph, g_wproj);
    __half* atth;  cudaGetSymbolAddress((void**)&atth, g_att);

    cvt_kernel<<<NX / 8 / 256, 256>>>(x, xh, NX);
    cvt_kernel<<<NWQ / 8 / 256, 256>>>(w_qkv, wqh, NWQ);
    cvt_kernel<<<NWP / 8 / 256, 256>>>(w_proj, wph, NWP);

    dim3 gq(3 * Dc / 128, M / 128);  // (18, 32)
    gemm_mma<0><<<gq, 256>>>(xh, wqh, b_qkv, nullptr, M, 3 * Dc, Dc);

    dim3 ga(Sc / 64, Bc * Hc);       // (32, 24)
    attn_mma<<<ga, 128>>>();

    dim3 gp(Dc / 128, M / 128);      // (6, 32)
    gemm_mma<1><<<gp, 256>>>(atth, wph, b_proj, out, M, Dc, Dc);
}

// round 10
// speedup vs baseline: 7.3765x; 1.0018x over previous
#include <cuda_runtime.h>
#include <cuda_fp16.h>

#define Bc 2
#define Sc 2048
#define Dc 768
#define Hc 12
#define HDc 64
#define QSCALE 0.125f   // 64^-0.5

// Scratch (allocation-free)
__device__ __half g_xh[Bc * Sc * Dc];
__device__ __half g_wqkv[Dc * 3 * Dc];
__device__ __half g_wproj[Dc * Dc];
__device__ __half g_q[Bc * Hc * Sc * HDc];
__device__ __half g_k[Bc * Hc * Sc * HDc];
__device__ __half g_v[Bc * Hc * Sc * HDc];
__device__ __half g_att[Bc * Sc * Dc];

// ---------------------------------------------------------------------------
// helpers
// ---------------------------------------------------------------------------
__device__ __forceinline__ unsigned pack2(float lo, float hi) {
    __half2 h = __floats2half2_rn(lo, hi);
    return *(unsigned*)&h;
}
__device__ __forceinline__ unsigned sptr(const void* p) {
    return (unsigned)__cvta_generic_to_shared(p);
}
__device__ __forceinline__ void mma16(float c[4], const unsigned a[4],
                                      unsigned b0, unsigned b1) {
    asm volatile(
        "mma.sync.aligned.m16n8k16.row.col.f32.f16.f16.f32 "
        "{%0,%1,%2,%3},{%4,%5,%6,%7},{%8,%9},{%0,%1,%2,%3};"
        : "+f"(c[0]), "+f"(c[1]), "+f"(c[2]), "+f"(c[3])
        : "r"(a[0]), "r"(a[1]), "r"(a[2]), "r"(a[3]), "r"(b0), "r"(b1));
}
__device__ __forceinline__ void ldm_x4(unsigned r[4], const void* p) {
    unsigned a = sptr(p);
    asm volatile("ldmatrix.sync.aligned.m8n8.x4.shared.b16 {%0,%1,%2,%3}, [%4];"
                 : "=r"(r[0]), "=r"(r[1]), "=r"(r[2]), "=r"(r[3]) : "r"(a));
}
__device__ __forceinline__ void ldm_x4_t(unsigned r[4], const void* p) {
    unsigned a = sptr(p);
    asm volatile("ldmatrix.sync.aligned.m8n8.x4.trans.shared.b16 {%0,%1,%2,%3}, [%4];"
                 : "=r"(r[0]), "=r"(r[1]), "=r"(r[2]), "=r"(r[3]) : "r"(a));
}
__device__ __forceinline__ void cpa16(void* s, const void* g) {
    asm volatile("cp.async.cg.shared.global [%0], [%1], 16;"
                 :: "r"(sptr(s)), "l"(g));
}
__device__ __forceinline__ void cp_commit() {
    asm volatile("cp.async.commit_group;");
}
template <int N> __device__ __forceinline__ void cp_wait() {
    asm volatile("cp.async.wait_group %0;" :: "n"(N));
}

// ---------------------------------------------------------------------------
// fp32 -> fp16 elementwise convert (8 elems/thread)
// ---------------------------------------------------------------------------
__global__ __launch_bounds__(256)
void cvt_kernel(const float* __restrict__ in, __half* __restrict__ out, int n)
{
    int i = (blockIdx.x * 256 + threadIdx.x) * 8;
    if (i >= n) return;
    float4 a = *(const float4*)(in + i);
    float4 b = *(const float4*)(in + i + 4);
    uint4 u;
    u.x = pack2(a.x, a.y); u.y = pack2(a.z, a.w);
    u.z = pack2(b.x, b.y); u.w = pack2(b.z, b.w);
    *(uint4*)(out + i) = u;
}

// ---------------------------------------------------------------------------
// fp16 GEMM, 3-stage cp.async multistage, ONE __syncthreads per k-step.
// Block 256 thr (8 warps 2x4), tile 128x128, k-step 32.
// Dynamic SMEM: 3*(128*40 + 32*136)*2 = 56832 B.
// MODE 0: scatter epilogue -> g_q(scaled)/g_k/g_v. MODE 1: out = C + bias.
// ---------------------------------------------------------------------------
#define GEMM_SMEM (3 * (128 * 40 + 32 * 136) * 2)

template <int MODE>
__global__ __launch_bounds__(256)
void gemm_mma(const __half* __restrict__ A, const __half* __restrict__ W,
              const float* __restrict__ bias, float* __restrict__ out,
              int M, int N, int K)
{
    extern __shared__ __align__(16) __half smp[];
    __half* AsB = smp;                   // [3][128][40]
    __half* BsB = smp + 3 * 128 * 40;    // [3][32][136]
#define ASP(s, r, c) (AsB + ((s) * 128 + (r)) * 40 + (c))
#define BSP(s, r, c) (BsB + ((s) * 32 + (r)) * 136 + (c))

    const int tid = threadIdx.x;
    const int lane = tid & 31, w = tid >> 5;
    const int g = lane >> 2, t4 = lane & 3;
    const int wm = w >> 2, wn = w & 3;
    const int row0 = blockIdx.y * 128, n0 = blockIdx.x * 128;

    float C[4][4][4];
#pragma unroll
    for (int mt = 0; mt < 4; mt++)
#pragma unroll
        for (int nt = 0; nt < 4; nt++)
#pragma unroll
            for (int i = 0; i < 4; i++) C[mt][nt][i] = 0.f;

    // per-thread cp.async chunk coords (512 chunks each, 2/thread)
    const int ar0 = (tid + 0)   >> 2, ac0 = ((tid + 0)   & 3) * 8;
    const int ar1 = (tid + 256) >> 2, ac1 = ((tid + 256) & 3) * 8;
    const int wr0 = (tid + 0)   >> 4, wc0 = ((tid + 0)   & 15) * 8;
    const int wr1 = (tid + 256) >> 4, wc1 = ((tid + 256) & 15) * 8;

    const int NIT = K / 32;
    // prologue: issue tiles 0 and 1
#pragma unroll
    for (int s = 0; s < 2; s++) {
        int kk = s * 32;
        cpa16(ASP(s, ar0, ac0), &A[(size_t)(row0 + ar0) * K + kk + ac0]);
        cpa16(ASP(s, ar1, ac1), &A[(size_t)(row0 + ar1) * K + kk + ac1]);
        cpa16(BSP(s, wr0, wc0), &W[(size_t)(kk + wr0) * N + n0 + wc0]);
        cpa16(BSP(s, wr1, wc1), &W[(size_t)(kk + wr1) * N + n0 + wc1]);
        cp_commit();
    }

    for (int it = 0; it < NIT; it++) {
        const int buf = it % 3;
        cp_wait<1>();
        __syncthreads();

        if (it + 2 < NIT) {                  // prefetch tile it+2
            int kk = (it + 2) * 32, s = (it + 2) % 3;
            cpa16(ASP(s, ar0, ac0), &A[(size_t)(row0 + ar0) * K + kk + ac0]);
            cpa16(ASP(s, ar1, ac1), &A[(size_t)(row0 + ar1) * K + kk + ac1]);
            cpa16(BSP(s, wr0, wc0), &W[(size_t)(kk + wr0) * N + n0 + wc0]);
            cpa16(BSP(s, wr1, wc1), &W[(size_t)(kk + wr1) * N + n0 + wc1]);
        }
        cp_commit();

#pragma unroll
        for (int sub = 0; sub < 2; sub++) {
            unsigned a[4][4], bfr[2][4];
            const int arow = wm * 64 + (lane & 7) + (lane & 8);
            const int acol = sub * 16 + ((lane & 16) >> 1);
#pragma unroll
            for (int mt = 0; mt < 4; mt++)
                ldm_x4(a[mt], ASP(buf, arow + mt * 16, acol));
            const int brow = sub * 16 + (lane & 7) + (lane & 8);
#pragma unroll
            for (int nh = 0; nh < 2; nh++)
                ldm_x4_t(bfr[nh], BSP(buf, brow, wn * 32 + nh * 16 + ((lane & 16) >> 1)));
#pragma unroll
            for (int mt = 0; mt < 4; mt++)
#pragma unroll
                for (int nt = 0; nt < 4; nt++)
                    mma16(C[mt][nt], a[mt],
                          bfr[nt >> 1][(nt & 1) * 2], bfr[nt >> 1][(nt & 1) * 2 + 1]);
        }
    }

    // epilogue
#pragma unroll
    for (int mt = 0; mt < 4; mt++) {
#pragma unroll
        for (int nt = 0; nt < 4; nt++) {
            int m = row0 + wm * 64 + mt * 16 + g;
            int n = n0 + wn * 32 + nt * 8 + 2 * t4;
#pragma unroll
            for (int half = 0; half < 2; half++) {
                int mm = m + half * 8;
#pragma unroll
                for (int dc = 0; dc < 2; dc++) {
                    int nn = n + dc;
                    float v = C[mt][nt][half * 2 + dc] + bias[nn];
                    if (MODE == 0) {
                        int which = nn / Dc;
                        int rr = nn - which * Dc;
                        int h = rr >> 6, hd = rr & 63;
                        int b = mm >> 11, s = mm & 2047;
                        int idx = ((b * Hc + h) * Sc + s) * HDc + hd;
                        if (which == 0)      g_q[idx] = __float2half(v * QSCALE);
                        else if (which == 1) g_k[idx] = __float2half(v);
                        else                 g_v[idx] = __float2half(v);
                    } else {
                        out[(size_t)mm * N + nn] = v;
                    }
                }
            }
        }
    }
#undef ASP
#undef BSP
}

// ---------------------------------------------------------------------------
// Flash attention, fp16 MMA, 3-stage cp.async KV pipeline, one sync per tile.
// Block 128 thr (4 warps), Q tile 64 rows (warp=16), KV tile 64 keys.
// Dynamic SMEM: (64*72 + 6*64*72)*2 = 64512 B.
// ---------------------------------------------------------------------------
#define ATTN_SMEM ((64 * 72 + 6 * 64 * 72) * 2)

__global__ __launch_bounds__(128)
void attn_mma()
{
    extern __shared__ __align__(16) __half smp[];
    __half* Qs  = smp;                    // [64][72]
    __half* KsB = smp + 64 * 72;          // [3][64][72]
    __half* VsB = KsB + 3 * 64 * 72;      // [3][64][72]
#define QSP(r, c) (Qs + (r) * 72 + (c))
#define KSP(s, r, c) (KsB + ((s) * 64 + (r)) * 72 + (c))
#define VSP(s, r, c) (VsB + ((s) * 64 + (r)) * 72 + (c))

    const int tid = threadIdx.x;
    const int lane = tid & 31, w = tid >> 5;
    const int g = lane >> 2, t4 = lane & 3;
    const int bh = blockIdx.y, q0 = blockIdx.x * 64;
    const int b = bh / Hc, h = bh - b * Hc;

    const __half* qb = g_q + ((size_t)bh * Sc + q0) * HDc;
    const __half* kb = g_k + (size_t)bh * Sc * HDc;
    const __half* vb = g_v + (size_t)bh * Sc * HDc;

    // per-thread KV chunk coords: 512 chunks -> 4/thread
    int cr[4], cc[4];
#pragma unroll
    for (int i = 0; i < 4; i++) {
        int e = tid + 128 * i;
        cr[i] = e >> 3; cc[i] = (e & 7) * 8;
    }

    // load Q + issue KV tiles 0,1
#pragma unroll
    for (int i = 0; i < 4; i++)
        *(uint4*)QSP(cr[i], cc[i]) = *(const uint4*)&qb[(size_t)cr[i] * 64 + cc[i]];
#pragma unroll
    for (int s = 0; s < 2; s++) {
        size_t off = (size_t)s * 64 * 64;
#pragma unroll
        for (int i = 0; i < 4; i++) {
            cpa16(KSP(s, cr[i], cc[i]), &kb[off + (size_t)cr[i] * 64 + cc[i]]);
            cpa16(VSP(s, cr[i], cc[i]), &vb[off + (size_t)cr[i] * 64 + cc[i]]);
        }
        cp_commit();
    }
    __syncthreads();   // Q visible

    // hoist Q fragments
    unsigned aq[4][4];
    {
        int r = w * 16 + g;
#pragma unroll
        for (int ks = 0; ks < 4; ks++) {
            aq[ks][0] = *(const unsigned*)QSP(r, ks * 16 + 2 * t4);
            aq[ks][1] = *(const unsigned*)QSP(r + 8, ks * 16 + 2 * t4);
            aq[ks][2] = *(const unsigned*)QSP(r, ks * 16 + 8 + 2 * t4);
            aq[ks][3] = *(const unsigned*)QSP(r + 8, ks * 16 + 8 + 2 * t4);
        }
    }

    float O[8][4];
#pragma unroll
    for (int nt = 0; nt < 8; nt++)
#pragma unroll
        for (int i = 0; i < 4; i++) O[nt][i] = 0.f;
    float m_lo = -1e30f, m_hi = -1e30f, l_lo = 0.f, l_hi = 0.f;

    const int NT = Sc / 64;
    for (int t = 0; t < NT; t++) {
        const int buf = t % 3;
        cp_wait<1>();
        __syncthreads();

        if (t + 2 < NT) {                    // prefetch KV tile t+2
            int s = (t + 2) % 3;
            size_t off = (size_t)(t + 2) * 64 * 64;
#pragma unroll
            for (int i = 0; i < 4; i++) {
                cpa16(KSP(s, cr[i], cc[i]), &kb[off + (size_t)cr[i] * 64 + cc[i]]);
                cpa16(VSP(s, cr[i], cc[i]), &vb[off + (size_t)cr[i] * 64 + cc[i]]);
            }
        }
        cp_commit();

        // -------- S = Q @ K^T --------
        float S[8][4];
#pragma unroll
        for (int nt = 0; nt < 8; nt++)
#pragma unroll
            for (int i = 0; i < 4; i++) S[nt][i] = 0.f;
#pragma unroll
        for (int ks = 0; ks < 4; ks++) {
            unsigned bk[4][4];
#pragma unroll
            for (int nh = 0; nh < 4; nh++) {
                int krow = nh * 16 + (lane & 7) + ((lane & 16) >> 1);
                int kcol = ks * 16 + (lane & 8);
                ldm_x4(bk[nh], KSP(buf, krow, kcol));
            }
#pragma unroll
            for (int nt = 0; nt < 8; nt++)
                mma16(S[nt], aq[ks],
                      bk[nt >> 1][(nt & 1) * 2], bk[nt >> 1][(nt & 1) * 2 + 1]);
        }

        // -------- online softmax --------
        float mx0 = -1e30f, mx1 = -1e30f;
#pragma unroll
        for (int nt = 0; nt < 8; nt++) {
            mx0 = fmaxf(mx0, fmaxf(S[nt][0], S[nt][1]));
            mx1 = fmaxf(mx1, fmaxf(S[nt][2], S[nt][3]));
        }
        mx0 = fmaxf(mx0, __shfl_xor_sync(0xffffffffu, mx0, 1));
        mx0 = fmaxf(mx0, __shfl_xor_sync(0xffffffffu, mx0, 2));
        mx1 = fmaxf(mx1, __shfl_xor_sync(0xffffffffu, mx1, 1));
        mx1 = fmaxf(mx1, __shfl_xor_sync(0xffffffffu, mx1, 2));

        float nm0 = fmaxf(m_lo, mx0), nm1 = fmaxf(m_hi, mx1);
        float al0 = __expf(m_lo - nm0), al1 = __expf(m_hi - nm1);
        m_lo = nm0; m_hi = nm1;

        float s0 = 0.f, s1 = 0.f;
#pragma unroll
        for (int nt = 0; nt < 8; nt++) {
            float p0 = __expf(S[nt][0] - nm0);
            float p1 = __expf(S[nt][1] - nm0);
            float p2 = __expf(S[nt][2] - nm1);
            float p3 = __expf(S[nt][3] - nm1);
            S[nt][0] = p0; S[nt][1] = p1; S[nt][2] = p2; S[nt][3] = p3;
            s0 += p0 + p1; s1 += p2 + p3;
        }
        s0 += __shfl_xor_sync(0xffffffffu, s0, 1);
        s0 += __shfl_xor_sync(0xffffffffu, s0, 2);
        s1 += __shfl_xor_sync(0xffffffffu, s1, 1);
        s1 += __shfl_xor_sync(0xffffffffu, s1, 2);
        l_lo = l_lo * al0 + s0;
        l_hi = l_hi * al1 + s1;

        // rescale O; pack P into PV A-fragments
#pragma unroll
        for (int nt = 0; nt < 8; nt++) {
            O[nt][0] *= al0; O[nt][1] *= al0;
            O[nt][2] *= al1; O[nt][3] *= al1;
        }
        unsigned ap[4][4];
#pragma unroll
        for (int ks = 0; ks < 4; ks++) {
            ap[ks][0] = pack2(S[2 * ks][0], S[2 * ks][1]);
            ap[ks][1] = pack2(S[2 * ks][2], S[2 * ks][3]);
            ap[ks][2] = pack2(S[2 * ks + 1][0], S[2 * ks + 1][1]);
            ap[ks][3] = pack2(S[2 * ks + 1][2], S[2 * ks + 1][3]);
        }

        // -------- O += P @ V --------
#pragma unroll
        for (int ks = 0; ks < 4; ks++) {
            unsigned bv[4][4];
#pragma unroll
            for (int nh = 0; nh < 4; nh++) {
                int vrow = ks * 16 + (lane & 7) + (lane & 8);
                int vcol = nh * 16 + ((lane & 16) >> 1);
                ldm_x4_t(bv[nh], VSP(buf, vrow, vcol));
            }
#pragma unroll
            for (int nt = 0; nt < 8; nt++)
                mma16(O[nt], ap[ks],
                      bv[nt >> 1][(nt & 1) * 2], bv[nt >> 1][(nt & 1) * 2 + 1]);
        }
    }

    // write normalized output (fp16)
    float inv0 = 1.f / l_lo, inv1 = 1.f / l_hi;
    __half* ob = g_att + ((size_t)(b * Sc + q0)) * Dc + h * HDc;
#pragma unroll
    for (int nt = 0; nt < 8; nt++) {
        int r = w * 16 + g, c = nt * 8 + 2 * t4;
        *(unsigned*)&ob[(size_t)r * Dc + c] = pack2(O[nt][0] * inv0, O[nt][1] * inv0);
        *(unsigned*)&ob[(size_t)(r + 8) * Dc + c] = pack2(O[nt][2] * inv1, O[nt][3] * inv1);
    }
#undef QSP
#undef KSP
#undef VSP
}

// ---------------------------------------------------------------------------
extern "C" void kernel_launch(void* const* d_in, const int* in_sizes, int n_in,
                              void* d_out, int out_size)
{
    (void)in_sizes; (void)n_in; (void)out_size;
    const float* x      = (const float*)d_in[0];
    const float* w_qkv  = (const float*)d_in[1];
    const float* b_qkv  = (const float*)d_in[2];
    const float* w_proj = (const float*)d_in[3];
    const float* b_proj = (const float*)d_in[4];
    float* out = (float*)d_out;

    const int M = Bc * Sc;  // 4096
    const int NX = Bc * Sc * Dc;
    const int NWQ = Dc * 3 * Dc;
    const int NWP = Dc * Dc;

    __half* xh;    cudaGetSymbolAddress((void**)&xh, g_xh);
    __half* wqh;   cudaGetSymbolAddress((void**)&wqh, g_wqkv);
    __half* wph;   cudaGetSymbolAddress((void**)&wph, g_wproj);
    __half* atth;  cudaGetSymbolAddress((void**)&atth, g_att);

    static bool attr_set = false;
    if (!attr_set) {
        cudaFuncSetAttribute(gemm_mma<0>, cudaFuncAttributeMaxDynamicSharedMemorySize, GEMM_SMEM);
        cudaFuncSetAttribute(gemm_mma<1>, cudaFuncAttributeMaxDynamicSharedMemorySize, GEMM_SMEM);
        cudaFuncSetAttribute(attn_mma, cudaFuncAttributeMaxDynamicSharedMemorySize, ATTN_SMEM);
        attr_set = true;
    }

    cvt_kernel<<<NX / 8 / 256, 256>>>(x, xh, NX);
    cvt_kernel<<<NWQ / 8 / 256, 256>>>(w_qkv, wqh, NWQ);
    cvt_kernel<<<NWP / 8 / 256, 256>>>(w_proj, wph, NWP);

    dim3 gq(3 * Dc / 128, M / 128);  // (18, 32)
    gemm_mma<0><<<gq, 256, GEMM_SMEM>>>(xh, wqh, b_qkv, nullptr, M, 3 * Dc, Dc);

    dim3 ga(Sc / 64, Bc * Hc);       // (32, 24)
    attn_mma<<<ga, 128, ATTN_SMEM>>>();

    dim3 gp(Dc / 128, M / 128);      // (6, 32)
    gemm_mma<1><<<gp, 256, GEMM_SMEM>>>(atth, wph, b_proj, out, M, Dc, Dc);
}

// round 14
// speedup vs baseline: 7.7604x; 1.0520x over previous
#include <cuda_runtime.h>
#include <cuda_fp16.h>

#define Bc 2
#define Sc 2048
#define Dc 768
#define Hc 12
#define HDc 64
#define QSCALE 0.125f   // 64^-0.5

// Scratch (allocation-free)
__device__ __half g_xh[Bc * Sc * Dc];
__device__ __half g_wqkv[Dc * 3 * Dc];
__device__ __half g_wproj[Dc * Dc];
__device__ __half g_q[Bc * Hc * Sc * HDc];
__device__ __half g_k[Bc * Hc * Sc * HDc];
__device__ __half g_v[Bc * Hc * Sc * HDc];
__device__ __half g_att[Bc * Sc * Dc];

// ---------------------------------------------------------------------------
// helpers
// ---------------------------------------------------------------------------
__device__ __forceinline__ unsigned pack2(float lo, float hi) {
    __half2 h = __floats2half2_rn(lo, hi);
    return *(unsigned*)&h;
}
__device__ __forceinline__ unsigned sptr(const void* p) {
    return (unsigned)__cvta_generic_to_shared(p);
}
__device__ __forceinline__ void mma16(float c[4], const unsigned a[4],
                                      unsigned b0, unsigned b1) {
    asm volatile(
        "mma.sync.aligned.m16n8k16.row.col.f32.f16.f16.f32 "
        "{%0,%1,%2,%3},{%4,%5,%6,%7},{%8,%9},{%0,%1,%2,%3};"
        : "+f"(c[0]), "+f"(c[1]), "+f"(c[2]), "+f"(c[3])
        : "r"(a[0]), "r"(a[1]), "r"(a[2]), "r"(a[3]), "r"(b0), "r"(b1));
}
__device__ __forceinline__ void ldm_x4(unsigned r[4], const void* p) {
    unsigned a = sptr(p);
    asm volatile("ldmatrix.sync.aligned.m8n8.x4.shared.b16 {%0,%1,%2,%3}, [%4];"
                 : "=r"(r[0]), "=r"(r[1]), "=r"(r[2]), "=r"(r[3]) : "r"(a));
}
__device__ __forceinline__ void ldm_x4_t(unsigned r[4], const void* p) {
    unsigned a = sptr(p);
    asm volatile("ldmatrix.sync.aligned.m8n8.x4.trans.shared.b16 {%0,%1,%2,%3}, [%4];"
                 : "=r"(r[0]), "=r"(r[1]), "=r"(r[2]), "=r"(r[3]) : "r"(a));
}
__device__ __forceinline__ void cpa16(void* s, const void* g) {
    asm volatile("cp.async.cg.shared.global [%0], [%1], 16;"
                 :: "r"(sptr(s)), "l"(g));
}
__device__ __forceinline__ void cp_commit() {
    asm volatile("cp.async.commit_group;");
}
template <int N> __device__ __forceinline__ void cp_wait() {
    asm volatile("cp.async.wait_group %0;" :: "n"(N));
}

// ---------------------------------------------------------------------------
// fp32 -> fp16 elementwise convert (8 elems/thread)
// ---------------------------------------------------------------------------
__global__ __launch_bounds__(256)
void cvt_kernel(const float* __restrict__ in, __half* __restrict__ out, int n)
{
    int i = (blockIdx.x * 256 + threadIdx.x) * 8;
    if (i >= n) return;
    float4 a = *(const float4*)(in + i);
    float4 b = *(const float4*)(in + i + 4);
    uint4 u;
    u.x = pack2(a.x, a.y); u.y = pack2(a.z, a.w);
    u.z = pack2(b.x, b.y); u.w = pack2(b.z, b.w);
    *(uint4*)(out + i) = u;
}

// ---------------------------------------------------------------------------
// fp16 GEMM, 3-stage cp.async, k-step 64 (4 k16 subs), ONE sync per k-step.
// Block 256 thr (8 warps 2x4), tile 128x128.
// Dynamic SMEM: 3*(128*72 + 64*136)*2 = 107520 B.
// MODE 0: scatter epilogue -> g_q(scaled)/g_k/g_v. MODE 1: out = C + bias.
// ---------------------------------------------------------------------------
#define GEMM_SMEM (3 * (128 * 72 + 64 * 136) * 2)

template <int MODE>
__global__ __launch_bounds__(256)
void gemm_mma(const __half* __restrict__ A, const __half* __restrict__ W,
              const float* __restrict__ bias, float* __restrict__ out,
              int M, int N, int K)
{
    extern __shared__ __align__(16) __half smp[];
    __half* AsB = smp;                   // [3][128][72]
    __half* BsB = smp + 3 * 128 * 72;    // [3][64][136]
#define ASP(s, r, c) (AsB + ((s) * 128 + (r)) * 72 + (c))
#define BSP(s, r, c) (BsB + ((s) * 64 + (r)) * 136 + (c))

    const int tid = threadIdx.x;
    const int lane = tid & 31, w = tid >> 5;
    const int g = lane >> 2, t4 = lane & 3;
    const int wm = w >> 2, wn = w & 3;
    const int row0 = blockIdx.y * 128, n0 = blockIdx.x * 128;

    float C[4][4][4];
#pragma unroll
    for (int mt = 0; mt < 4; mt++)
#pragma unroll
        for (int nt = 0; nt < 4; nt++)
#pragma unroll
            for (int i = 0; i < 4; i++) C[mt][nt][i] = 0.f;

    // per-thread cp.async chunk coords (1024 chunks each, 4/thread)
    int ar[4], ac[4], wr[4], wc[4];
#pragma unroll
    for (int i = 0; i < 4; i++) {
        int e = tid + 256 * i;
        ar[i] = e >> 3;  ac[i] = (e & 7) * 8;    // A: 128 rows x 8 chunks
        wr[i] = e >> 4;  wc[i] = (e & 15) * 8;   // W:  64 rows x 16 chunks
    }

    const int NIT = K / 64;   // 12
    // prologue: issue tiles 0 and 1
#pragma unroll
    for (int s = 0; s < 2; s++) {
        int kk = s * 64;
#pragma unroll
        for (int i = 0; i < 4; i++) {
            cpa16(ASP(s, ar[i], ac[i]), &A[(size_t)(row0 + ar[i]) * K + kk + ac[i]]);
            cpa16(BSP(s, wr[i], wc[i]), &W[(size_t)(kk + wr[i]) * N + n0 + wc[i]]);
        }
        cp_commit();
    }

    for (int it = 0; it < NIT; it++) {
        const int buf = it % 3;
        cp_wait<1>();
        __syncthreads();

        if (it + 2 < NIT) {                  // prefetch tile it+2
            int kk = (it + 2) * 64, s = (it + 2) % 3;
#pragma unroll
            for (int i = 0; i < 4; i++) {
                cpa16(ASP(s, ar[i], ac[i]), &A[(size_t)(row0 + ar[i]) * K + kk + ac[i]]);
                cpa16(BSP(s, wr[i], wc[i]), &W[(size_t)(kk + wr[i]) * N + n0 + wc[i]]);
            }
        }
        cp_commit();

#pragma unroll
        for (int sub = 0; sub < 4; sub++) {
            unsigned a[4][4], bfr[2][4];
            const int arow = wm * 64 + (lane & 7) + (lane & 8);
            const int acol = sub * 16 + ((lane & 16) >> 1);
#pragma unroll
            for (int mt = 0; mt < 4; mt++)
                ldm_x4(a[mt], ASP(buf, arow + mt * 16, acol));
            const int brow = sub * 16 + (lane & 7) + (lane & 8);
#pragma unroll
            for (int nh = 0; nh < 2; nh++)
                ldm_x4_t(bfr[nh], BSP(buf, brow, wn * 32 + nh * 16 + ((lane & 16) >> 1)));
#pragma unroll
            for (int mt = 0; mt < 4; mt++)
#pragma unroll
                for (int nt = 0; nt < 4; nt++)
                    mma16(C[mt][nt], a[mt],
                          bfr[nt >> 1][(nt & 1) * 2], bfr[nt >> 1][(nt & 1) * 2 + 1]);
        }
    }

    // epilogue
#pragma unroll
    for (int mt = 0; mt < 4; mt++) {
#pragma unroll
        for (int nt = 0; nt < 4; nt++) {
            int m = row0 + wm * 64 + mt * 16 + g;
            int n = n0 + wn * 32 + nt * 8 + 2 * t4;
#pragma unroll
            for (int half = 0; half < 2; half++) {
                int mm = m + half * 8;
#pragma unroll
                for (int dc = 0; dc < 2; dc++) {
                    int nn = n + dc;
                    float v = C[mt][nt][half * 2 + dc] + bias[nn];
                    if (MODE == 0) {
                        int which = nn / Dc;
                        int rr = nn - which * Dc;
                        int h = rr >> 6, hd = rr & 63;
                        int b = mm >> 11, s = mm & 2047;
                        int idx = ((b * Hc + h) * Sc + s) * HDc + hd;
                        if (which == 0)      g_q[idx] = __float2half(v * QSCALE);
                        else if (which == 1) g_k[idx] = __float2half(v);
                        else                 g_v[idx] = __float2half(v);
                    } else {
                        out[(size_t)mm * N + nn] = v;
                    }
                }
            }
        }
    }
#undef ASP
#undef BSP
}

// ---------------------------------------------------------------------------
// Flash attention, fp16 MMA, 3-stage cp.async KV pipeline, one sync per tile.
// Block 256 thr (8 warps x 16 Q rows = 128-row Q tile), KV tile 64 keys.
// Dynamic SMEM: (128*72 + 6*64*72)*2 = 73728 B.  grid: (S/128, B*H) = (16,24).
// ---------------------------------------------------------------------------
#define ATTN_SMEM ((128 * 72 + 6 * 64 * 72) * 2)

__global__ __launch_bounds__(256)
void attn_mma()
{
    extern __shared__ __align__(16) __half smp[];
    __half* Qs  = smp;                    // [128][72]
    __half* KsB = smp + 128 * 72;         // [3][64][72]
    __half* VsB = KsB + 3 * 64 * 72;      // [3][64][72]
#define QSP(r, c) (Qs + (r) * 72 + (c))
#define KSP(s, r, c) (KsB + ((s) * 64 + (r)) * 72 + (c))
#define VSP(s, r, c) (VsB + ((s) * 64 + (r)) * 72 + (c))

    const int tid = threadIdx.x;
    const int lane = tid & 31, w = tid >> 5;          // w = 0..7
    const int g = lane >> 2, t4 = lane & 3;
    const int bh = blockIdx.y, q0 = blockIdx.x * 128;
    const int b = bh / Hc, h = bh - b * Hc;

    const __half* qb = g_q + ((size_t)bh * Sc + q0) * HDc;
    const __half* kb = g_k + (size_t)bh * Sc * HDc;
    const __half* vb = g_v + (size_t)bh * Sc * HDc;

    // Q: 128x64 halves = 1024 chunks -> 4/thread. KV: 512 chunks -> 2/thread.
    int qr[4], qc[4];
#pragma unroll
    for (int i = 0; i < 4; i++) {
        int e = tid + 256 * i;
        qr[i] = e >> 3; qc[i] = (e & 7) * 8;
    }
    int cr[2], cc[2];
#pragma unroll
    for (int i = 0; i < 2; i++) {
        int e = tid + 256 * i;
        cr[i] = e >> 3; cc[i] = (e & 7) * 8;
    }

    // load Q + issue KV tiles 0,1
#pragma unroll
    for (int i = 0; i < 4; i++)
        *(uint4*)QSP(qr[i], qc[i]) = *(const uint4*)&qb[(size_t)qr[i] * 64 + qc[i]];
#pragma unroll
    for (int s = 0; s < 2; s++) {
        size_t off = (size_t)s * 64 * 64;
#pragma unroll
        for (int i = 0; i < 2; i++) {
            cpa16(KSP(s, cr[i], cc[i]), &kb[off + (size_t)cr[i] * 64 + cc[i]]);
            cpa16(VSP(s, cr[i], cc[i]), &vb[off + (size_t)cr[i] * 64 + cc[i]]);
        }
        cp_commit();
    }
    __syncthreads();   // Q visible

    // hoist Q fragments (warp w owns rows w*16 .. w*16+15)
    unsigned aq[4][4];
    {
        int r = w * 16 + g;
#pragma unroll
        for (int ks = 0; ks < 4; ks++) {
            aq[ks][0] = *(const unsigned*)QSP(r, ks * 16 + 2 * t4);
            aq[ks][1] = *(const unsigned*)QSP(r + 8, ks * 16 + 2 * t4);
            aq[ks][2] = *(const unsigned*)QSP(r, ks * 16 + 8 + 2 * t4);
            aq[ks][3] = *(const unsigned*)QSP(r + 8, ks * 16 + 8 + 2 * t4);
        }
    }

    float O[8][4];
#pragma unroll
    for (int nt = 0; nt < 8; nt++)
#pragma unroll
        for (int i = 0; i < 4; i++) O[nt][i] = 0.f;
    float m_lo = -1e30f, m_hi = -1e30f, l_lo = 0.f, l_hi = 0.f;

    const int NT = Sc / 64;
    for (int t = 0; t < NT; t++) {
        const int buf = t % 3;
        cp_wait<1>();
        __syncthreads();

        if (t + 2 < NT) {                    // prefetch KV tile t+2
            int s = (t + 2) % 3;
            size_t off = (size_t)(t + 2) * 64 * 64;
#pragma unroll
            for (int i = 0; i < 2; i++) {
                cpa16(KSP(s, cr[i], cc[i]), &kb[off + (size_t)cr[i] * 64 + cc[i]]);
                cpa16(VSP(s, cr[i], cc[i]), &vb[off + (size_t)cr[i] * 64 + cc[i]]);
            }
        }
        cp_commit();

        // -------- S = Q @ K^T --------
        float S[8][4];
#pragma unroll
        for (int nt = 0; nt < 8; nt++)
#pragma unroll
            for (int i = 0; i < 4; i++) S[nt][i] = 0.f;
#pragma unroll
        for (int ks = 0; ks < 4; ks++) {
            unsigned bk[4][4];
#pragma unroll
            for (int nh = 0; nh < 4; nh++) {
                int krow = nh * 16 + (lane & 7) + ((lane & 16) >> 1);
                int kcol = ks * 16 + (lane & 8);
                ldm_x4(bk[nh], KSP(buf, krow, kcol));
            }
#pragma unroll
            for (int nt = 0; nt < 8; nt++)
                mma16(S[nt], aq[ks],
                      bk[nt >> 1][(nt & 1) * 2], bk[nt >> 1][(nt & 1) * 2 + 1]);
        }

        // -------- online softmax --------
        float mx0 = -1e30f, mx1 = -1e30f;
#pragma unroll
        for (int nt = 0; nt < 8; nt++) {
            mx0 = fmaxf(mx0, fmaxf(S[nt][0], S[nt][1]));
            mx1 = fmaxf(mx1, fmaxf(S[nt][2], S[nt][3]));
        }
        mx0 = fmaxf(mx0, __shfl_xor_sync(0xffffffffu, mx0, 1));
        mx0 = fmaxf(mx0, __shfl_xor_sync(0xffffffffu, mx0, 2));
        mx1 = fmaxf(mx1, __shfl_xor_sync(0xffffffffu, mx1, 1));
        mx1 = fmaxf(mx1, __shfl_xor_sync(0xffffffffu, mx1, 2));

        float nm0 = fmaxf(m_lo, mx0), nm1 = fmaxf(m_hi, mx1);
        float al0 = __expf(m_lo - nm0), al1 = __expf(m_hi - nm1);
        m_lo = nm0; m_hi = nm1;

        float s0 = 0.f, s1 = 0.f;
#pragma unroll
        for (int nt = 0; nt < 8; nt++) {
            float p0 = __expf(S[nt][0] - nm0);
            float p1 = __expf(S[nt][1] - nm0);
            float p2 = __expf(S[nt][2] - nm1);
            float p3 = __expf(S[nt][3] - nm1);
            S[nt][0] = p0; S[nt][1] = p1; S[nt][2] = p2; S[nt][3] = p3;
            s0 += p0 + p1; s1 += p2 + p3;
        }
        s0 += __shfl_xor_sync(0xffffffffu, s0, 1);
        s0 += __shfl_xor_sync(0xffffffffu, s0, 2);
        s1 += __shfl_xor_sync(0xffffffffu, s1, 1);
        s1 += __shfl_xor_sync(0xffffffffu, s1, 2);
        l_lo = l_lo * al0 + s0;
        l_hi = l_hi * al1 + s1;

        // rescale O; pack P into PV A-fragments
#pragma unroll
        for (int nt = 0; nt < 8; nt++) {
            O[nt][0] *= al0; O[nt][1] *= al0;
            O[nt][2] *= al1; O[nt][3] *= al1;
        }
        unsigned ap[4][4];
#pragma unroll
        for (int ks = 0; ks < 4; ks++) {
            ap[ks][0] = pack2(S[2 * ks][0], S[2 * ks][1]);
            ap[ks][1] = pack2(S[2 * ks][2], S[2 * ks][3]);
            ap[ks][2] = pack2(S[2 * ks + 1][0], S[2 * ks + 1][1]);
            ap[ks][3] = pack2(S[2 * ks + 1][2], S[2 * ks + 1][3]);
        }

        // -------- O += P @ V --------
#pragma unroll
        for (int ks = 0; ks < 4; ks++) {
            unsigned bv[4][4];
#pragma unroll
            for (int nh = 0; nh < 4; nh++) {
                int vrow = ks * 16 + (lane & 7) + (lane & 8);
                int vcol = nh * 16 + ((lane & 16) >> 1);
                ldm_x4_t(bv[nh], VSP(buf, vrow, vcol));
            }
#pragma unroll
            for (int nt = 0; nt < 8; nt++)
                mma16(O[nt], ap[ks],
                      bv[nt >> 1][(nt & 1) * 2], bv[nt >> 1][(nt & 1) * 2 + 1]);
        }
    }

    // write normalized output (fp16)
    float inv0 = 1.f / l_lo, inv1 = 1.f / l_hi;
    __half* ob = g_att + ((size_t)(b * Sc + q0)) * Dc + h * HDc;
#pragma unroll
    for (int nt = 0; nt < 8; nt++) {
        int r = w * 16 + g, c = nt * 8 + 2 * t4;
        *(unsigned*)&ob[(size_t)r * Dc + c] = pack2(O[nt][0] * inv0, O[nt][1] * inv0);
        *(unsigned*)&ob[(size_t)(r + 8) * Dc + c] = pack2(O[nt][2] * inv1, O[nt][3] * inv1);
    }
#undef QSP
#undef KSP
#undef VSP
}

// ---------------------------------------------------------------------------
extern "C" void kernel_launch(void* const* d_in, const int* in_sizes, int n_in,
                              void* d_out, int out_size)
{
    (void)in_sizes; (void)n_in; (void)out_size;
    const float* x      = (const float*)d_in[0];
    const float* w_qkv  = (const float*)d_in[1];
    const float* b_qkv  = (const float*)d_in[2];
    const float* w_proj = (const float*)d_in[3];
    const float* b_proj = (const float*)d_in[4];
    float* out = (float*)d_out;

    const int M = Bc * Sc;  // 4096
    const int NX = Bc * Sc * Dc;
    const int NWQ = Dc * 3 * Dc;
    const int NWP = Dc * Dc;

    __half* xh;    cudaGetSymbolAddress((void**)&xh, g_xh);
    __half* wqh;   cudaGetSymbolAddress((void**)&wqh, g_wqkv);
    __half* wph;   cudaGetSymbolAddress((void**)&wph, g_wproj);
    __half* atth;  cudaGetSymbolAddress((void**)&atth, g_att);

    static bool attr_set = false;
    if (!attr_set) {
        cudaFuncSetAttribute(gemm_mma<0>, cudaFuncAttributeMaxDynamicSharedMemorySize, GEMM_SMEM);
        cudaFuncSetAttribute(gemm_mma<1>, cudaFuncAttributeMaxDynamicSharedMemorySize, GEMM_SMEM);
        cudaFuncSetAttribute(attn_mma, cudaFuncAttributeMaxDynamicSharedMemorySize, ATTN_SMEM);
        attr_set = true;
    }

    cvt_kernel<<<NX / 8 / 256, 256>>>(x, xh, NX);
    cvt_kernel<<<NWQ / 8 / 256, 256>>>(w_qkv, wqh, NWQ);
    cvt_kernel<<<NWP / 8 / 256, 256>>>(w_proj, wph, NWP);

    dim3 gq(3 * Dc / 128, M / 128);  // (18, 32)
    gemm_mma<0><<<gq, 256, GEMM_SMEM>>>(xh, wqh, b_qkv, nullptr, M, 3 * Dc, Dc);

    dim3 ga(Sc / 128, Bc * Hc);      // (16, 24)
    attn_mma<<<ga, 256, ATTN_SMEM>>>();

    dim3 gp(Dc / 128, M / 128);      // (6, 32)
    gemm_mma<1><<<gp, 256, GEMM_SMEM>>>(atth, wph, b_proj, out, M, Dc, Dc);
}

// round 16
// speedup vs baseline: 8.0749x; 1.0405x over previous
#include <cuda_runtime.h>
#include <cuda_fp16.h>

#define Bc 2
#define Sc 2048
#define Dc 768
#define Hc 12
#define HDc 64
#define QSCALE2 0.18033688011112042f   // 64^-0.5 * log2(e)

// Scratch (allocation-free)
__device__ __half g_xh[Bc * Sc * Dc];
__device__ __half g_wqkv[Dc * 3 * Dc];
__device__ __half g_wproj[Dc * Dc];
__device__ __half g_q[Bc * Hc * Sc * HDc];   // pre-scaled by QSCALE2 (log2 domain)
__device__ __half g_k[Bc * Hc * Sc * HDc];
__device__ __half g_v[Bc * Hc * Sc * HDc];
__device__ __half g_att[Bc * Sc * Dc];

// ---------------------------------------------------------------------------
// helpers
// ---------------------------------------------------------------------------
__device__ __forceinline__ unsigned pack2(float lo, float hi) {
    __half2 h = __floats2half2_rn(lo, hi);
    return *(unsigned*)&h;
}
__device__ __forceinline__ unsigned sptr(const void* p) {
    return (unsigned)__cvta_generic_to_shared(p);
}
__device__ __forceinline__ void mma16(float c[4], const unsigned a[4],
                                      unsigned b0, unsigned b1) {
    asm volatile(
        "mma.sync.aligned.m16n8k16.row.col.f32.f16.f16.f32 "
        "{%0,%1,%2,%3},{%4,%5,%6,%7},{%8,%9},{%0,%1,%2,%3};"
        : "+f"(c[0]), "+f"(c[1]), "+f"(c[2]), "+f"(c[3])
        : "r"(a[0]), "r"(a[1]), "r"(a[2]), "r"(a[3]), "r"(b0), "r"(b1));
}
__device__ __forceinline__ void ldm_x4(unsigned r[4], const void* p) {
    unsigned a = sptr(p);
    asm volatile("ldmatrix.sync.aligned.m8n8.x4.shared.b16 {%0,%1,%2,%3}, [%4];"
                 : "=r"(r[0]), "=r"(r[1]), "=r"(r[2]), "=r"(r[3]) : "r"(a));
}
__device__ __forceinline__ void ldm_x4_t(unsigned r[4], const void* p) {
    unsigned a = sptr(p);
    asm volatile("ldmatrix.sync.aligned.m8n8.x4.trans.shared.b16 {%0,%1,%2,%3}, [%4];"
                 : "=r"(r[0]), "=r"(r[1]), "=r"(r[2]), "=r"(r[3]) : "r"(a));
}
__device__ __forceinline__ void cpa16(void* s, const void* g) {
    asm volatile("cp.async.cg.shared.global [%0], [%1], 16;"
                 :: "r"(sptr(s)), "l"(g));
}
__device__ __forceinline__ void cp_commit() {
    asm volatile("cp.async.commit_group;");
}
template <int N> __device__ __forceinline__ void cp_wait() {
    asm volatile("cp.async.wait_group %0;" :: "n"(N));
}

// ---------------------------------------------------------------------------
// fused fp32->fp16 convert of x, w_qkv, w_proj in ONE launch.
// Segment boundaries fall on block boundaries: 1536 / 864 / 288 blocks.
// ---------------------------------------------------------------------------
#define CVT_C0 (Bc * Sc * Dc / 8)            // 393216 threads for x
#define CVT_C1 (Dc * 3 * Dc / 8)             // 221184 threads for w_qkv
#define CVT_C2 (Dc * Dc / 8)                 //  73728 threads for w_proj
#define CVT_BLOCKS ((CVT_C0 + CVT_C1 + CVT_C2) / 256)   // 2688

__global__ __launch_bounds__(256)
void cvt3_kernel(const float* __restrict__ x, __half* __restrict__ xh,
                 const float* __restrict__ wq, __half* __restrict__ wqh,
                 const float* __restrict__ wp, __half* __restrict__ wph)
{
    int gid = blockIdx.x * 256 + threadIdx.x;
    const float* in; __half* out; int i;
    if (gid < CVT_C0)              { in = x;  out = xh;  i = gid * 8; }
    else if (gid < CVT_C0 + CVT_C1){ in = wq; out = wqh; i = (gid - CVT_C0) * 8; }
    else                           { in = wp; out = wph; i = (gid - CVT_C0 - CVT_C1) * 8; }
    float4 a = *(const float4*)(in + i);
    float4 b = *(const float4*)(in + i + 4);
    uint4 u;
    u.x = pack2(a.x, a.y); u.y = pack2(a.z, a.w);
    u.z = pack2(b.x, b.y); u.w = pack2(b.z, b.w);
    *(uint4*)(out + i) = u;
}

// ---------------------------------------------------------------------------
// fp16 GEMM, 3-stage cp.async, k-step 64 (4 k16 subs), ONE sync per k-step.
// Block 256 thr (8 warps 2x4), tile 128x128.
// Dynamic SMEM: 3*(128*72 + 64*136)*2 = 107520 B.
// MODE 0: scatter epilogue -> g_q(scaled, log2-domain)/g_k/g_v. MODE 1: out.
// ---------------------------------------------------------------------------
#define GEMM_SMEM (3 * (128 * 72 + 64 * 136) * 2)

template <int MODE>
__global__ __launch_bounds__(256)
void gemm_mma(const __half* __restrict__ A, const __half* __restrict__ W,
              const float* __restrict__ bias, float* __restrict__ out,
              int M, int N, int K)
{
    extern __shared__ __align__(16) __half smp[];
    __half* AsB = smp;                   // [3][128][72]
    __half* BsB = smp + 3 * 128 * 72;    // [3][64][136]
#define ASP(s, r, c) (AsB + ((s) * 128 + (r)) * 72 + (c))
#define BSP(s, r, c) (BsB + ((s) * 64 + (r)) * 136 + (c))

    const int tid = threadIdx.x;
    const int lane = tid & 31, w = tid >> 5;
    const int g = lane >> 2, t4 = lane & 3;
    const int wm = w >> 2, wn = w & 3;
    const int row0 = blockIdx.y * 128, n0 = blockIdx.x * 128;

    float C[4][4][4];
#pragma unroll
    for (int mt = 0; mt < 4; mt++)
#pragma unroll
        for (int nt = 0; nt < 4; nt++)
#pragma unroll
            for (int i = 0; i < 4; i++) C[mt][nt][i] = 0.f;

    int ar[4], ac[4], wr[4], wc[4];
#pragma unroll
    for (int i = 0; i < 4; i++) {
        int e = tid + 256 * i;
        ar[i] = e >> 3;  ac[i] = (e & 7) * 8;
        wr[i] = e >> 4;  wc[i] = (e & 15) * 8;
    }

    const int NIT = K / 64;   // 12
#pragma unroll
    for (int s = 0; s < 2; s++) {
        int kk = s * 64;
#pragma unroll
        for (int i = 0; i < 4; i++) {
            cpa16(ASP(s, ar[i], ac[i]), &A[(size_t)(row0 + ar[i]) * K + kk + ac[i]]);
            cpa16(BSP(s, wr[i], wc[i]), &W[(size_t)(kk + wr[i]) * N + n0 + wc[i]]);
        }
        cp_commit();
    }

    for (int it = 0; it < NIT; it++) {
        const int buf = it % 3;
        cp_wait<1>();
        __syncthreads();

        if (it + 2 < NIT) {
            int kk = (it + 2) * 64, s = (it + 2) % 3;
#pragma unroll
            for (int i = 0; i < 4; i++) {
                cpa16(ASP(s, ar[i], ac[i]), &A[(size_t)(row0 + ar[i]) * K + kk + ac[i]]);
                cpa16(BSP(s, wr[i], wc[i]), &W[(size_t)(kk + wr[i]) * N + n0 + wc[i]]);
            }
        }
        cp_commit();

#pragma unroll
        for (int sub = 0; sub < 4; sub++) {
            unsigned a[4][4], bfr[2][4];
            const int arow = wm * 64 + (lane & 7) + (lane & 8);
            const int acol = sub * 16 + ((lane & 16) >> 1);
#pragma unroll
            for (int mt = 0; mt < 4; mt++)
                ldm_x4(a[mt], ASP(buf, arow + mt * 16, acol));
            const int brow = sub * 16 + (lane & 7) + (lane & 8);
#pragma unroll
            for (int nh = 0; nh < 2; nh++)
                ldm_x4_t(bfr[nh], BSP(buf, brow, wn * 32 + nh * 16 + ((lane & 16) >> 1)));
#pragma unroll
            for (int mt = 0; mt < 4; mt++)
#pragma unroll
                for (int nt = 0; nt < 4; nt++)
                    mma16(C[mt][nt], a[mt],
                          bfr[nt >> 1][(nt & 1) * 2], bfr[nt >> 1][(nt & 1) * 2 + 1]);
        }
    }

    // epilogue
#pragma unroll
    for (int mt = 0; mt < 4; mt++) {
#pragma unroll
        for (int nt = 0; nt < 4; nt++) {
            int m = row0 + wm * 64 + mt * 16 + g;
            int n = n0 + wn * 32 + nt * 8 + 2 * t4;
#pragma unroll
            for (int half = 0; half < 2; half++) {
                int mm = m + half * 8;
#pragma unroll
                for (int dc = 0; dc < 2; dc++) {
                    int nn = n + dc;
                    float v = C[mt][nt][half * 2 + dc] + bias[nn];
                    if (MODE == 0) {
                        int which = nn / Dc;
                        int rr = nn - which * Dc;
                        int h = rr >> 6, hd = rr & 63;
                        int b = mm >> 11, s = mm & 2047;
                        int idx = ((b * Hc + h) * Sc + s) * HDc + hd;
                        if (which == 0)      g_q[idx] = __float2half(v * QSCALE2);
                        else if (which == 1) g_k[idx] = __float2half(v);
                        else                 g_v[idx] = __float2half(v);
                    } else {
                        out[(size_t)mm * N + nn] = v;
                    }
                }
            }
        }
    }
#undef ASP
#undef BSP
}

// ---------------------------------------------------------------------------
// Flash attention, fp16 MMA, 3-stage cp.async KV pipeline, one sync per tile.
// Block 256 thr (8 warps x 16 Q rows = 128-row Q tile), KV tile 64 keys.
// Softmax in base-2 domain (Q pre-scaled by log2(e)*scale; exp2f = raw EX2).
// Dynamic SMEM: (128*72 + 6*64*72)*2 = 73728 B.  grid: (16, 24).
// ---------------------------------------------------------------------------
#define ATTN_SMEM ((128 * 72 + 6 * 64 * 72) * 2)

__global__ __launch_bounds__(256)
void attn_mma()
{
    extern __shared__ __align__(16) __half smp[];
    __half* Qs  = smp;
    __half* KsB = smp + 128 * 72;
    __half* VsB = KsB + 3 * 64 * 72;
#define QSP(r, c) (Qs + (r) * 72 + (c))
#define KSP(s, r, c) (KsB + ((s) * 64 + (r)) * 72 + (c))
#define VSP(s, r, c) (VsB + ((s) * 64 + (r)) * 72 + (c))

    const int tid = threadIdx.x;
    const int lane = tid & 31, w = tid >> 5;
    const int g = lane >> 2, t4 = lane & 3;
    const int bh = blockIdx.y, q0 = blockIdx.x * 128;
    const int b = bh / Hc, h = bh - b * Hc;

    const __half* qb = g_q + ((size_t)bh * Sc + q0) * HDc;
    const __half* kb = g_k + (size_t)bh * Sc * HDc;
    const __half* vb = g_v + (size_t)bh * Sc * HDc;

    int qr[4], qc[4];
#pragma unroll
    for (int i = 0; i < 4; i++) {
        int e = tid + 256 * i;
        qr[i] = e >> 3; qc[i] = (e & 7) * 8;
    }
    int cr[2], cc[2];
#pragma unroll
    for (int i = 0; i < 2; i++) {
        int e = tid + 256 * i;
        cr[i] = e >> 3; cc[i] = (e & 7) * 8;
    }

#pragma unroll
    for (int i = 0; i < 4; i++)
        *(uint4*)QSP(qr[i], qc[i]) = *(const uint4*)&qb[(size_t)qr[i] * 64 + qc[i]];
#pragma unroll
    for (int s = 0; s < 2; s++) {
        size_t off = (size_t)s * 64 * 64;
#pragma unroll
        for (int i = 0; i < 2; i++) {
            cpa16(KSP(s, cr[i], cc[i]), &kb[off + (size_t)cr[i] * 64 + cc[i]]);
            cpa16(VSP(s, cr[i], cc[i]), &vb[off + (size_t)cr[i] * 64 + cc[i]]);
        }
        cp_commit();
    }
    __syncthreads();

    unsigned aq[4][4];
    {
        int r = w * 16 + g;
#pragma unroll
        for (int ks = 0; ks < 4; ks++) {
            aq[ks][0] = *(const unsigned*)QSP(r, ks * 16 + 2 * t4);
            aq[ks][1] = *(const unsigned*)QSP(r + 8, ks * 16 + 2 * t4);
            aq[ks][2] = *(const unsigned*)QSP(r, ks * 16 + 8 + 2 * t4);
            aq[ks][3] = *(const unsigned*)QSP(r + 8, ks * 16 + 8 + 2 * t4);
        }
    }

    float O[8][4];
#pragma unroll
    for (int nt = 0; nt < 8; nt++)
#pragma unroll
        for (int i = 0; i < 4; i++) O[nt][i] = 0.f;
    float m_lo = -1e30f, m_hi = -1e30f, l_lo = 0.f, l_hi = 0.f;

    const int NT = Sc / 64;
    for (int t = 0; t < NT; t++) {
        const int buf = t % 3;
        cp_wait<1>();
        __syncthreads();

        if (t + 2 < NT) {
            int s = (t + 2) % 3;
            size_t off = (size_t)(t + 2) * 64 * 64;
#pragma unroll
            for (int i = 0; i < 2; i++) {
                cpa16(KSP(s, cr[i], cc[i]), &kb[off + (size_t)cr[i] * 64 + cc[i]]);
                cpa16(VSP(s, cr[i], cc[i]), &vb[off + (size_t)cr[i] * 64 + cc[i]]);
            }
        }
        cp_commit();

        // -------- S = Q @ K^T  (log2-domain logits) --------
        float S[8][4];
#pragma unroll
        for (int nt = 0; nt < 8; nt++)
#pragma unroll
            for (int i = 0; i < 4; i++) S[nt][i] = 0.f;
#pragma unroll
        for (int ks = 0; ks < 4; ks++) {
            unsigned bk[4][4];
#pragma unroll
            for (int nh = 0; nh < 4; nh++) {
                int krow = nh * 16 + (lane & 7) + ((lane & 16) >> 1);
                int kcol = ks * 16 + (lane & 8);
                ldm_x4(bk[nh], KSP(buf, krow, kcol));
            }
#pragma unroll
            for (int nt = 0; nt < 8; nt++)
                mma16(S[nt], aq[ks],
                      bk[nt >> 1][(nt & 1) * 2], bk[nt >> 1][(nt & 1) * 2 + 1]);
        }

        // -------- online softmax (base-2) --------
        float mx0 = -1e30f, mx1 = -1e30f;
#pragma unroll
        for (int nt = 0; nt < 8; nt++) {
            mx0 = fmaxf(mx0, fmaxf(S[nt][0], S[nt][1]));
            mx1 = fmaxf(mx1, fmaxf(S[nt][2], S[nt][3]));
        }
        mx0 = fmaxf(mx0, __shfl_xor_sync(0xffffffffu, mx0, 1));
        mx0 = fmaxf(mx0, __shfl_xor_sync(0xffffffffu, mx0, 2));
        mx1 = fmaxf(mx1, __shfl_xor_sync(0xffffffffu, mx1, 1));
        mx1 = fmaxf(mx1, __shfl_xor_sync(0xffffffffu, mx1, 2));

        float nm0 = fmaxf(m_lo, mx0), nm1 = fmaxf(m_hi, mx1);
        float al0 = exp2f(m_lo - nm0), al1 = exp2f(m_hi - nm1);
        m_lo = nm0; m_hi = nm1;

        float s0 = 0.f, s1 = 0.f;
#pragma unroll
        for (int nt = 0; nt < 8; nt++) {
            float p0 = exp2f(S[nt][0] - nm0);
            float p1 = exp2f(S[nt][1] - nm0);
            float p2 = exp2f(S[nt][2] - nm1);
            float p3 = exp2f(S[nt][3] - nm1);
            S[nt][0] = p0; S[nt][1] = p1; S[nt][2] = p2; S[nt][3] = p3;
            s0 += p0 + p1; s1 += p2 + p3;
        }
        s0 += __shfl_xor_sync(0xffffffffu, s0, 1);
        s0 += __shfl_xor_sync(0xffffffffu, s0, 2);
        s1 += __shfl_xor_sync(0xffffffffu, s1, 1);
        s1 += __shfl_xor_sync(0xffffffffu, s1, 2);
        l_lo = l_lo * al0 + s0;
        l_hi = l_hi * al1 + s1;

#pragma unroll
        for (int nt = 0; nt < 8; nt++) {
            O[nt][0] *= al0; O[nt][1] *= al0;
            O[nt][2] *= al1; O[nt][3] *= al1;
        }
        unsigned ap[4][4];
#pragma unroll
        for (int ks = 0; ks < 4; ks++) {
            ap[ks][0] = pack2(S[2 * ks][0], S[2 * ks][1]);
            ap[ks][1] = pack2(S[2 * ks][2], S[2 * ks][3]);
            ap[ks][2] = pack2(S[2 * ks + 1][0], S[2 * ks + 1][1]);
            ap[ks][3] = pack2(S[2 * ks + 1][2], S[2 * ks + 1][3]);
        }

        // -------- O += P @ V --------
#pragma unroll
        for (int ks = 0; ks < 4; ks++) {
            unsigned bv[4][4];
#pragma unroll
            for (int nh = 0; nh < 4; nh++) {
                int vrow = ks * 16 + (lane & 7) + (lane & 8);
                int vcol = nh * 16 + ((lane & 16) >> 1);
                ldm_x4_t(bv[nh], VSP(buf, vrow, vcol));
            }
#pragma unroll
            for (int nt = 0; nt < 8; nt++)
                mma16(O[nt], ap[ks],
                      bv[nt >> 1][(nt & 1) * 2], bv[nt >> 1][(nt & 1) * 2 + 1]);
        }
    }

    float inv0 = 1.f / l_lo, inv1 = 1.f / l_hi;
    __half* ob = g_att + ((size_t)(b * Sc + q0)) * Dc + h * HDc;
#pragma unroll
    for (int nt = 0; nt < 8; nt++) {
        int r = w * 16 + g, c = nt * 8 + 2 * t4;
        *(unsigned*)&ob[(size_t)r * Dc + c] = pack2(O[nt][0] * inv0, O[nt][1] * inv0);
        *(unsigned*)&ob[(size_t)(r + 8) * Dc + c] = pack2(O[nt][2] * inv1, O[nt][3] * inv1);
    }
#undef QSP
#undef KSP
#undef VSP
}

// ---------------------------------------------------------------------------
extern "C" void kernel_launch(void* const* d_in, const int* in_sizes, int n_in,
                              void* d_out, int out_size)
{
    (void)in_sizes; (void)n_in; (void)out_size;
    const float* x      = (const float*)d_in[0];
    const float* w_qkv  = (const float*)d_in[1];
    const float* b_qkv  = (const float*)d_in[2];
    const float* w_proj = (const float*)d_in[3];
    const float* b_proj = (const float*)d_in[4];
    float* out = (float*)d_out;

    const int M = Bc * Sc;  // 4096

    __half* xh;    cudaGetSymbolAddress((void**)&xh, g_xh);
    __half* wqh;   cudaGetSymbolAddress((void**)&wqh, g_wqkv);
    __half* wph;   cudaGetSymbolAddress((void**)&wph, g_wproj);
    __half* atth;  cudaGetSymbolAddress((void**)&atth, g_att);

    static bool attr_set = false;
    if (!attr_set) {
        cudaFuncSetAttribute(gemm_mma<0>, cudaFuncAttributeMaxDynamicSharedMemorySize, GEMM_SMEM);
        cudaFuncSetAttribute(gemm_mma<1>, cudaFuncAttributeMaxDynamicSharedMemorySize, GEMM_SMEM);
        cudaFuncSetAttribute(attn_mma, cudaFuncAttributeMaxDynamicSharedMemorySize, ATTN_SMEM);
        attr_set = true;
    }

    // single fused convert launch
    cvt3_kernel<<<CVT_BLOCKS, 256>>>(x, xh, w_qkv, wqh, w_proj, wph);

    dim3 gq(3 * Dc / 128, M / 128);  // (18, 32)
    gemm_mma<0><<<gq, 256, GEMM_SMEM>>>(xh, wqh, b_qkv, nullptr, M, 3 * Dc, Dc);

    dim3 ga(Sc / 128, Bc * Hc);      // (16, 24)
    attn_mma<<<ga, 256, ATTN_SMEM>>>();

    dim3 gp(Dc / 128, M / 128);      // (6, 32)
    gemm_mma<1><<<gp, 256, GEMM_SMEM>>>(atth, wph, b_proj, out, M, Dc, Dc);
}